// round 9
// baseline (speedup 1.0000x reference)
#include <cuda_runtime.h>
#include <cuda_fp16.h>
#include <math.h>
#include <stdint.h>

#define C_IN   64
#define C_OUT  64
#define NBASIS 9
#define TILE_M 64
#define MAX_T  1600000
#define MAX_F  400000
#define BN_EPS 1e-3f

// ---- scratch (device globals; no allocation allowed) ----
__device__ __half g_contrib[(size_t)MAX_T * C_OUT];  // 204.8 MB (fp16)
__device__ float  g_prebn[(size_t)MAX_F * C_OUT];    // 102.4 MB
__device__ int    g_offs[MAX_F];
__device__ int    g_blk[1024];
__device__ float  g_stats[2 * C_OUT];

// ================= exclusive-scan of num_texture =================
__global__ void scan1_kernel(const int* __restrict__ cnt, int F) {
    __shared__ int s[1024];
    int tid = threadIdx.x;
    int f = blockIdx.x * 1024 + tid;
    int c = (f < F) ? cnt[f] : 0;
    s[tid] = c;
    __syncthreads();
    for (int off = 1; off < 1024; off <<= 1) {
        int v = (tid >= off) ? s[tid - off] : 0;
        __syncthreads();
        s[tid] += v;
        __syncthreads();
    }
    if (f < F) g_offs[f] = s[tid] - c;
    if (tid == 1023) g_blk[blockIdx.x] = s[1023];
}
__global__ void scan2_kernel(int nb) {
    __shared__ int s[1024];
    int tid = threadIdx.x;
    int c = (tid < nb) ? g_blk[tid] : 0;
    s[tid] = c;
    __syncthreads();
    for (int off = 1; off < 1024; off <<= 1) {
        int v = (tid >= off) ? s[tid - off] : 0;
        __syncthreads();
        s[tid] += v;
        __syncthreads();
    }
    if (tid < nb) g_blk[tid] = s[tid] - c;
}
__global__ void scan3_kernel(int F) {
    int f = blockIdx.x * 1024 + threadIdx.x;
    if (f < F) g_offs[f] += g_blk[blockIdx.x];
}

// ================= mma.sync GEMM: 64x8 warp tiles, cp.async pipeline =======
// contrib[t,o] = sum_k bary[t,k] * ( sum_i x[t,i] * W[o,i,k] )
//
// SMEM per CTA (104960 B -> 2 CTAs per SM):
//   Wh : [kb*64+o] rows of 128B, XOR-swizzled 16B chunks   = 73728
//   Xf : fp32 staging, 64 rows x 272B (pad)                = 17408
//   Ax : fp16, 64 rows x 144B (pad)                        =  9216
//   Bp : 2 x permuted bary fp32 [kb*64 + gid*4 + mt]       =  4608
#define SM_W      0
#define SM_XF     73728
#define XF_STRIDE 272
#define SM_AX     91136
#define SM_BP     100352
#define SMEM_GEMM 104960

#define MMA16816(d, a0, a1, a2, a3, b0, b1)                                 \
    asm volatile(                                                           \
        "mma.sync.aligned.m16n8k16.row.col.f32.f16.f16.f32 "                \
        "{%0,%1,%2,%3},{%4,%5,%6,%7},{%8,%9},{%0,%1,%2,%3};"                \
        : "+f"((d)[0]), "+f"((d)[1]), "+f"((d)[2]), "+f"((d)[3])            \
        : "r"(a0), "r"(a1), "r"(a2), "r"(a3), "r"(b0), "r"(b1))

__device__ __forceinline__ void ldsm4(uint32_t* r, uint32_t addr) {
    asm volatile("ldmatrix.sync.aligned.m8n8.x4.shared.b16 {%0,%1,%2,%3}, [%4];"
                 : "=r"(r[0]), "=r"(r[1]), "=r"(r[2]), "=r"(r[3]) : "r"(addr));
}
__device__ __forceinline__ void cpasync16(uint32_t dst, const void* src, int sz) {
    asm volatile("cp.async.cg.shared.global [%0], [%1], 16, %2;"
                 :: "r"(dst), "l"(src), "r"(sz));
}
#define CP_COMMIT() asm volatile("cp.async.commit_group;" ::: "memory")
#define CP_WAIT0()  asm volatile("cp.async.wait_group 0;" ::: "memory")

__global__ void __launch_bounds__(256, 2) gemm_mma_kernel(
    const float* __restrict__ X,     // [T, 64]
    const float* __restrict__ BARY,  // [T, 9]
    const float* __restrict__ W,     // [64, 64, 9]  (o, i, k)
    int T, int numTiles)
{
    extern __shared__ char sm[];
    const uint32_t smb = (uint32_t)__cvta_generic_to_shared(sm);

    const int tid  = threadIdx.x;
    const int wid  = tid >> 5;       // 0..7 : 8-column band
    const int lane = tid & 31;
    const int gid  = lane >> 2;
    const int tid4 = lane & 3;

    // ---- cp.async mapping: thread (row, q) loads 4x16B of X row ----
    const int crow = tid >> 2;       // 0..63
    const int cq   = tid & 3;        // quarter of the 256B row

    // ---- prologue: issue cp.async for tile0 + LDG bary(tile0) ----
    int tile = blockIdx.x;
    float by[3];
    {
        int t = tile * TILE_M + crow;
        const float* src = X + (size_t)t * C_IN + cq * 16;
        uint32_t dst = smb + SM_XF + crow * XF_STRIDE + cq * 64;
        int sz = (t < T) ? 16 : 0;
        #pragma unroll
        for (int c = 0; c < 4; c++) cpasync16(dst + c * 16, src + c * 4, sz);
        CP_COMMIT();
        #pragma unroll
        for (int c = 0; c < 3; c++) {
            int linear = tid * 3 + c;
            by[c] = 0.0f;
            if (linear < TILE_M * NBASIS) {
                int tl = linear / NBASIS;
                int kb = linear - tl * NBASIS;
                int t2 = tile * TILE_M + tl;
                if (t2 < T) by[c] = BARY[(size_t)t2 * NBASIS + kb];
            }
        }
    }

    // ---- convert W once: swizzled rows [kb*64+o][i], 128B rows ----
    for (int idx = tid; idx < C_OUT * C_IN * NBASIS; idx += 256) {
        int o   = idx / (C_IN * NBASIS);
        int rem = idx - o * (C_IN * NBASIS);
        int i   = rem / NBASIS;
        int k   = rem - i * NBASIS;
        uint32_t byte = (uint32_t)(k * 64 + o) * 128
                      + ((((uint32_t)i >> 3) ^ (uint32_t)(o & 7)) << 4)
                      + (i & 7) * 2;
        *(__half*)(sm + byte) = __float2half_rn(W[idx]);
    }

    // ---- per-thread LDSM addresses ----
    uint32_t a_base[4];
    #pragma unroll
    for (int mt = 0; mt < 4; mt++)
        a_base[mt] = smb + SM_AX + (uint32_t)(mt * 16 + (lane & 15)) * 144
                   + ((lane >> 4) << 4);
    const int n_lane = wid * 8 + (lane & 7);
    const uint32_t b_row = smb + SM_W + (uint32_t)n_lane * 128;
    const int j_lane = lane >> 3;            // 0..3
    const uint32_t chunkA = (uint32_t)((j_lane)     ^ (n_lane & 7)) << 4;
    const uint32_t chunkB = (uint32_t)((j_lane + 4) ^ (n_lane & 7)) << 4;

    int buf = 0;
    for (; tile < numTiles; tile += gridDim.x) {
        const int t0 = tile * TILE_M;

        // ---- wait Xf; convert fp32 -> fp16 Ax; store permuted bary ----
        CP_WAIT0();
        {
            const float4* xfp = (const float4*)(sm + SM_XF + crow * XF_STRIDE + cq * 64);
            uint32_t h[8];
            #pragma unroll
            for (int jj = 0; jj < 4; jj++) {
                float4 v = xfp[jj];
                __half2 h0 = __floats2half2_rn(v.x, v.y);
                __half2 h1 = __floats2half2_rn(v.z, v.w);
                h[2 * jj]     = *(uint32_t*)&h0;
                h[2 * jj + 1] = *(uint32_t*)&h1;
            }
            uint4* dst = (uint4*)(sm + SM_AX + crow * 144 + cq * 32);
            dst[0] = make_uint4(h[0], h[1], h[2], h[3]);
            dst[1] = make_uint4(h[4], h[5], h[6], h[7]);

            float* bp = (float*)(sm + SM_BP + buf * 2304);
            #pragma unroll
            for (int c = 0; c < 3; c++) {
                int linear = tid * 3 + c;
                if (linear < TILE_M * NBASIS) {
                    int tl = linear / NBASIS;
                    int kb = linear - tl * NBASIS;
                    bp[kb * 64 + (tl & 15) * 4 + (tl >> 4)] = by[c];
                }
            }
        }
        __syncthreads();   // Ax + bary visible; Xf consumed by all warps

        // ---- issue cp.async + bary LDG for next tile ----
        {
            int ntile = tile + gridDim.x;
            if (ntile < numTiles) {
                int t = ntile * TILE_M + crow;
                const float* src = X + (size_t)t * C_IN + cq * 16;
                uint32_t dst = smb + SM_XF + crow * XF_STRIDE + cq * 64;
                int sz = (t < T) ? 16 : 0;
                #pragma unroll
                for (int c = 0; c < 4; c++) cpasync16(dst + c * 16, src + c * 4, sz);
                CP_COMMIT();
                #pragma unroll
                for (int c = 0; c < 3; c++) {
                    int linear = tid * 3 + c;
                    by[c] = 0.0f;
                    if (linear < TILE_M * NBASIS) {
                        int tl = linear / NBASIS;
                        int kb = linear - tl * NBASIS;
                        int t2 = ntile * TILE_M + tl;
                        if (t2 < T) by[c] = BARY[(size_t)t2 * NBASIS + kb];
                    }
                }
            } else {
                CP_COMMIT();   // keep wait_group balanced
            }
        }

        // ---- load all A fragments (64 rows, K=64) ----
        uint32_t afr[4][4][4];
        #pragma unroll
        for (int mt = 0; mt < 4; mt++)
            #pragma unroll
            for (int ks = 0; ks < 4; ks++)
                ldsm4(afr[mt][ks], a_base[mt] + ks * 32);
        __syncthreads();   // all ldsm done -> Ax free for next convert

        const float* bp = (const float*)(sm + SM_BP + buf * 2304);

        float acc[4][4];
        #pragma unroll
        for (int mt = 0; mt < 4; mt++)
            #pragma unroll
            for (int e = 0; e < 4; e++) acc[mt][e] = 0.0f;

        #pragma unroll 1
        for (int kb = 0; kb < NBASIS; kb++) {
            uint32_t bq0[4], bq1[4];
            const uint32_t kb_off = (uint32_t)kb * 8192;
            ldsm4(bq0, b_row + kb_off + chunkA);
            ldsm4(bq1, b_row + kb_off + chunkB);

            float tac[4][4];
            #pragma unroll
            for (int mt = 0; mt < 4; mt++)
                #pragma unroll
                for (int e = 0; e < 4; e++) tac[mt][e] = 0.0f;

            #pragma unroll
            for (int ks = 0; ks < 4; ks++) {
                uint32_t b0 = (ks < 2) ? bq0[(ks & 1) * 2]     : bq1[(ks & 1) * 2];
                uint32_t b1 = (ks < 2) ? bq0[(ks & 1) * 2 + 1] : bq1[(ks & 1) * 2 + 1];
                #pragma unroll
                for (int mt = 0; mt < 4; mt++)
                    MMA16816(tac[mt], afr[mt][ks][0], afr[mt][ks][1],
                             afr[mt][ks][2], afr[mt][ks][3], b0, b1);
            }

            float4 blo = *(const float4*)(bp + kb * 64 + gid * 4);
            float4 bhi = *(const float4*)(bp + kb * 64 + (gid + 8) * 4);
            acc[0][0] += blo.x * tac[0][0]; acc[0][1] += blo.x * tac[0][1];
            acc[0][2] += bhi.x * tac[0][2]; acc[0][3] += bhi.x * tac[0][3];
            acc[1][0] += blo.y * tac[1][0]; acc[1][1] += blo.y * tac[1][1];
            acc[1][2] += bhi.y * tac[1][2]; acc[1][3] += bhi.y * tac[1][3];
            acc[2][0] += blo.z * tac[2][0]; acc[2][1] += blo.z * tac[2][1];
            acc[2][2] += bhi.z * tac[2][2]; acc[2][3] += bhi.z * tac[2][3];
            acc[3][0] += blo.w * tac[3][0]; acc[3][1] += blo.w * tac[3][1];
            acc[3][2] += bhi.w * tac[3][2]; acc[3][3] += bhi.w * tac[3][3];
        }

        // ---- store 64x8 warp tile as fp16 ----
        {
            int col = wid * 8 + tid4 * 2;
            #pragma unroll
            for (int mt = 0; mt < 4; mt++) {
                int t = t0 + mt * 16 + gid;
                if (t < T) {
                    __half2 h = __floats2half2_rn(acc[mt][0], acc[mt][1]);
                    *(__half2*)&g_contrib[(size_t)t * C_OUT + col] = h;
                }
                if (t + 8 < T) {
                    __half2 h = __floats2half2_rn(acc[mt][2], acc[mt][3]);
                    *(__half2*)&g_contrib[(size_t)(t + 8) * C_OUT + col] = h;
                }
            }
        }
        buf ^= 1;
    }
}

// ================= facet mean + bias + relu + fused BN stats =================
__global__ void facet_kernel(const int* __restrict__ cnt,
                             const float* __restrict__ bias, int F) {
    __shared__ float ssum[64], ssq[64];
    int tid = threadIdx.x;
    if (tid < 64) { ssum[tid] = 0.0f; ssq[tid] = 0.0f; }
    __syncthreads();

    int gw   = (blockIdx.x * blockDim.x + tid) >> 5;
    int lane = tid & 31;
    int nw   = (gridDim.x * blockDim.x) >> 5;
    float b0 = bias[2 * lane];
    float b1 = bias[2 * lane + 1];
    float a0 = 0.0f, a1 = 0.0f, q0 = 0.0f, q1 = 0.0f;

    for (int f = gw; f < F; f += nw) {
        int start = g_offs[f];
        int c = cnt[f];
        float s0 = 0.0f, s1 = 0.0f;
        for (int r = 0; r < c; r++) {
            const __half2* row = (const __half2*)(g_contrib + (size_t)(start + r) * C_OUT);
            float2 v = __half22float2(row[lane]);
            s0 += v.x;
            s1 += v.y;
        }
        float inv = (c > 0) ? (1.0f / (float)c) : 0.0f;
        float v0 = fmaxf(s0 * inv + b0, 0.0f);
        float v1 = fmaxf(s1 * inv + b1, 0.0f);
        *(float2*)&g_prebn[(size_t)f * C_OUT + 2 * lane] = make_float2(v0, v1);
        a0 += v0; q0 += v0 * v0;
        a1 += v1; q1 += v1 * v1;
    }
    atomicAdd(&ssum[2 * lane],     a0);
    atomicAdd(&ssq[2 * lane],      q0);
    atomicAdd(&ssum[2 * lane + 1], a1);
    atomicAdd(&ssq[2 * lane + 1],  q1);
    __syncthreads();
    if (tid < 64) {
        atomicAdd(&g_stats[tid],      ssum[tid]);
        atomicAdd(&g_stats[64 + tid], ssq[tid]);
    }
}

__global__ void zero_stats_kernel() {
    if (threadIdx.x < 2 * C_OUT) g_stats[threadIdx.x] = 0.0f;
}

// ================= batchnorm apply =================
__global__ void bn_kernel(const float* __restrict__ gamma,
                          const float* __restrict__ beta,
                          float* __restrict__ out, int F) {
    int idx = blockIdx.x * blockDim.x + threadIdx.x;
    int total = F * (C_OUT / 4);
    float invF = 1.0f / (float)F;
    for (; idx < total; idx += gridDim.x * blockDim.x) {
        int o = (idx & 15) * 4;
        float4 v = *(const float4*)&g_prebn[(size_t)idx * 4];
        float4 r;
        #pragma unroll
        for (int j = 0; j < 4; j++) {
            float mu  = g_stats[o + j] * invF;
            float var = g_stats[C_OUT + o + j] * invF - mu * mu;
            float sc  = rsqrtf(var + BN_EPS) * gamma[o + j];
            float bb  = beta[o + j];
            float x   = (&v.x)[j];
            (&r.x)[j] = (x - mu) * sc + bb;
        }
        *(float4*)&out[(size_t)idx * 4] = r;
    }
}

// ================= launch =================
extern "C" void kernel_launch(void* const* d_in, const int* in_sizes, int n_in,
                              void* d_out, int out_size) {
    const float* X     = (const float*)d_in[0];
    const float* BARY  = (const float*)d_in[1];
    const float* W     = (const float*)d_in[2];
    const float* bias  = (const float*)d_in[3];
    const float* gamma = (const float*)d_in[4];
    const float* beta  = (const float*)d_in[5];
    const int*   cnt   = (const int*)d_in[6];

    int T = in_sizes[0] / C_IN;
    int F = in_sizes[6];
    int numTiles = (T + TILE_M - 1) / TILE_M;

    int sms = 148;
    cudaDeviceGetAttribute(&sms, cudaDevAttrMultiProcessorCount, 0);
    cudaFuncSetAttribute(gemm_mma_kernel, cudaFuncAttributeMaxDynamicSharedMemorySize, SMEM_GEMM);

    int nb = (F + 1023) / 1024;
    scan1_kernel<<<nb, 1024>>>(cnt, F);
    scan2_kernel<<<1, 1024>>>(nb);
    scan3_kernel<<<nb, 1024>>>(F);

    gemm_mma_kernel<<<2 * sms, 256, SMEM_GEMM>>>(X, BARY, W, T, numTiles);

    zero_stats_kernel<<<1, 128>>>();
    facet_kernel<<<2048, 256>>>(cnt, bias, F);

    bn_kernel<<<2048, 256>>>(gamma, beta, (float*)d_out, F);
}

// round 10
// speedup vs baseline: 1.1961x; 1.1961x over previous
#include <cuda_runtime.h>
#include <cuda_fp16.h>
#include <math.h>
#include <stdint.h>

#define C_IN   64
#define C_OUT  64
#define NBASIS 9
#define TILE_M 128
#define MAX_T  1600000
#define MAX_F  400000
#define BN_EPS 1e-3f

// ---- scratch (device globals; no allocation allowed) ----
__device__ __half g_contrib[(size_t)MAX_T * C_OUT];  // 204.8 MB (fp16)
__device__ __half g_prebn[(size_t)MAX_F * C_OUT];    // 51.2 MB (fp16)
__device__ int    g_offs[MAX_F];
__device__ int    g_blk[1024];
__device__ float  g_stats[2 * C_OUT];

// ================= exclusive-scan of num_texture =================
__global__ void scan1_kernel(const int* __restrict__ cnt, int F) {
    __shared__ int s[1024];
    int tid = threadIdx.x;
    int f = blockIdx.x * 1024 + tid;
    int c = (f < F) ? cnt[f] : 0;
    s[tid] = c;
    __syncthreads();
    for (int off = 1; off < 1024; off <<= 1) {
        int v = (tid >= off) ? s[tid - off] : 0;
        __syncthreads();
        s[tid] += v;
        __syncthreads();
    }
    if (f < F) g_offs[f] = s[tid] - c;
    if (tid == 1023) g_blk[blockIdx.x] = s[1023];
}
__global__ void scan2_kernel(int nb) {
    __shared__ int s[1024];
    int tid = threadIdx.x;
    int c = (tid < nb) ? g_blk[tid] : 0;
    s[tid] = c;
    __syncthreads();
    for (int off = 1; off < 1024; off <<= 1) {
        int v = (tid >= off) ? s[tid - off] : 0;
        __syncthreads();
        s[tid] += v;
        __syncthreads();
    }
    if (tid < nb) g_blk[tid] = s[tid] - c;
}
__global__ void scan3_kernel(int F) {
    int f = blockIdx.x * 1024 + threadIdx.x;
    if (f < F) g_offs[f] += g_blk[blockIdx.x];
    if (blockIdx.x == 0 && threadIdx.x < 2 * C_OUT) g_stats[threadIdx.x] = 0.0f;
}

// ================= mma.sync GEMM (R8 core, verbatim) ======================
// contrib[t,o] = sum_k ( (x[t,:] * bary[t,k]) fp16 ) @ W_k[o,:]^T
//
// SMEM per CTA (96912 B -> two CTAs per SM):
//   Wh  : [kb*64+o] rows of 128 B, XOR-swizzled 16B chunks  = 73728 B
//   Ax  : [t] rows, pad-72 halfs (144 B)                    = 18432 B
//   Bsh : 2 x [kb*132 + t] fp16                             =  4752 B
#define SM_W      0
#define SM_AX     73728
#define SM_BS     92160
#define BS_HALFS  1188            // 9 * 132
#define SMEM_GEMM 96912

#define MMA16816(d, a0, a1, a2, a3, b0, b1)                                 \
    asm volatile(                                                           \
        "mma.sync.aligned.m16n8k16.row.col.f32.f16.f16.f32 "                \
        "{%0,%1,%2,%3},{%4,%5,%6,%7},{%8,%9},{%0,%1,%2,%3};"                \
        : "+f"((d)[0]), "+f"((d)[1]), "+f"((d)[2]), "+f"((d)[3])            \
        : "r"(a0), "r"(a1), "r"(a2), "r"(a3), "r"(b0), "r"(b1))

__device__ __forceinline__ void ldsm4(uint32_t* r, uint32_t addr) {
    asm volatile("ldmatrix.sync.aligned.m8n8.x4.shared.b16 {%0,%1,%2,%3}, [%4];"
                 : "=r"(r[0]), "=r"(r[1]), "=r"(r[2]), "=r"(r[3]) : "r"(addr));
}
__device__ __forceinline__ uint32_t hmul2u(uint32_t a, uint32_t b) {
    __half2 r = __hmul2(*(__half2*)&a, *(__half2*)&b);
    return *(uint32_t*)&r;
}

__global__ void __launch_bounds__(256, 2) gemm_mma_kernel(
    const float* __restrict__ X,     // [T, 64]
    const float* __restrict__ BARY,  // [T, 9]
    const float* __restrict__ W,     // [64, 64, 9]  (o, i, k)
    int T, int numTiles)
{
    extern __shared__ char sm[];
    const uint32_t smb = (uint32_t)__cvta_generic_to_shared(sm);
    __half* Bsh = (__half*)(sm + SM_BS);

    const int tid  = threadIdx.x;
    const int wid  = tid >> 5;
    const int lane = tid & 31;
    const int gid  = lane >> 2;
    const int warp_m = wid >> 1;     // 0..3
    const int warp_n = wid & 1;      // 0..1
    const int rbase  = warp_m * 32;

    // ---- convert W once: swizzled rows [kb*64+o][i], 128B rows ----
    for (int idx = tid; idx < C_OUT * C_IN * NBASIS; idx += 256) {
        int o   = idx / (C_IN * NBASIS);
        int rem = idx - o * (C_IN * NBASIS);
        int i   = rem / NBASIS;
        int k   = rem - i * NBASIS;
        uint32_t byte = (uint32_t)(k * 64 + o) * 128
                      + ((((uint32_t)i >> 3) ^ (uint32_t)(o & 7)) << 4)
                      + (i & 7) * 2;
        *(__half*)(sm + byte) = __float2half_rn(W[idx]);
    }

    // ---- per-thread LDSM addresses ----
    uint32_t a_base[2];
    #pragma unroll
    for (int mt = 0; mt < 2; mt++)
        a_base[mt] = smb + SM_AX
                   + (uint32_t)(rbase + mt * 16 + (lane & 15)) * 144
                   + ((lane >> 4) << 4);
    uint32_t b_base[2];
    int s_p[2];
    const int kh = (lane >> 3) & 1;
    #pragma unroll
    for (int p = 0; p < 2; p++) {
        int n_local = warp_n * 32 + p * 16 + ((lane >> 4) & 1) * 8 + (lane & 7);
        b_base[p] = smb + SM_W + (uint32_t)n_local * 128;
        s_p[p] = n_local & 7;
    }

    // ---- prefetch lane mapping ----
    const int prow = tid >> 1;       // 0..127
    const int phf  = tid & 1;
    const int kb0  = phf ? 5 : 0;
    const int nby  = phf ? 4 : 5;

    uint32_t pk[16];
    float    by[5];

    int tile = blockIdx.x;
    {   // prologue prefetch
        int t = tile * TILE_M + prow;
        if (t < T) {
            const float4* xp = (const float4*)(X + (size_t)t * C_IN + phf * 32);
            #pragma unroll
            for (int j = 0; j < 8; j++) {
                float4 v = xp[j];
                __half2 h0 = __floats2half2_rn(v.x, v.y);
                __half2 h1 = __floats2half2_rn(v.z, v.w);
                pk[2 * j]     = *(uint32_t*)&h0;
                pk[2 * j + 1] = *(uint32_t*)&h1;
            }
            #pragma unroll
            for (int j = 0; j < 5; j++)
                if (j < nby) by[j] = BARY[(size_t)t * NBASIS + kb0 + j];
        } else {
            #pragma unroll
            for (int j = 0; j < 16; j++) pk[j] = 0u;
            #pragma unroll
            for (int j = 0; j < 5; j++) by[j] = 0.0f;
        }
    }
    __syncthreads();   // W ready

    int buf = 0;
    for (; tile < numTiles; tile += gridDim.x) {
        const int t0 = tile * TILE_M;

        // ---- store phase: regs -> SMEM ----
        {
            uint4* dst = (uint4*)(sm + SM_AX + prow * 144 + phf * 64);
            #pragma unroll
            for (int c = 0; c < 4; c++)
                dst[c] = make_uint4(pk[4 * c], pk[4 * c + 1], pk[4 * c + 2], pk[4 * c + 3]);
            __half* BsB = Bsh + buf * BS_HALFS;
            #pragma unroll
            for (int j = 0; j < 5; j++)
                if (j < nby) BsB[(kb0 + j) * 132 + prow] = __float2half_rn(by[j]);
        }
        __syncthreads();   // barrier A: stores visible

        // ---- load A fragments ONCE per tile ----
        uint32_t afr[2][4][4];
        #pragma unroll
        for (int mt = 0; mt < 2; mt++)
            #pragma unroll
            for (int ks = 0; ks < 4; ks++)
                ldsm4(afr[mt][ks], a_base[mt] + ks * 32);
        __syncthreads();   // barrier B: Ax free for next tile

        // ---- prefetch next tile (hidden under MMA below) ----
        {
            int ntile = tile + gridDim.x;
            if (ntile < numTiles) {
                int t = ntile * TILE_M + prow;
                if (t < T) {
                    const float4* xp = (const float4*)(X + (size_t)t * C_IN + phf * 32);
                    #pragma unroll
                    for (int j = 0; j < 8; j++) {
                        float4 v = xp[j];
                        __half2 h0 = __floats2half2_rn(v.x, v.y);
                        __half2 h1 = __floats2half2_rn(v.z, v.w);
                        pk[2 * j]     = *(uint32_t*)&h0;
                        pk[2 * j + 1] = *(uint32_t*)&h1;
                    }
                    #pragma unroll
                    for (int j = 0; j < 5; j++)
                        if (j < nby) by[j] = BARY[(size_t)t * NBASIS + kb0 + j];
                } else {
                    #pragma unroll
                    for (int j = 0; j < 16; j++) pk[j] = 0u;
                    #pragma unroll
                    for (int j = 0; j < 5; j++) by[j] = 0.0f;
                }
            }
        }

        const __half* BsB = Bsh + buf * BS_HALFS;

        float acc[2][4][4];
        #pragma unroll
        for (int mt = 0; mt < 2; mt++)
            #pragma unroll
            for (int nt = 0; nt < 4; nt++)
                #pragma unroll
                for (int e = 0; e < 4; e++) acc[mt][nt][e] = 0.0f;

        #pragma unroll 1
        for (int kb = 0; kb < NBASIS; kb++) {
            uint32_t bb0[2], bb1[2];
            #pragma unroll
            for (int mt = 0; mt < 2; mt++) {
                int r = rbase + mt * 16 + gid;
                __half2 h0 = __half2half2(BsB[kb * 132 + r]);
                __half2 h1 = __half2half2(BsB[kb * 132 + r + 8]);
                bb0[mt] = *(uint32_t*)&h0;
                bb1[mt] = *(uint32_t*)&h1;
            }

            const uint32_t kb_off = (uint32_t)kb * 8192;

            #pragma unroll
            for (int ks = 0; ks < 4; ks++) {
                uint32_t sa0[4], sa1[4];
                sa0[0] = hmul2u(afr[0][ks][0], bb0[0]);
                sa0[1] = hmul2u(afr[0][ks][1], bb1[0]);
                sa0[2] = hmul2u(afr[0][ks][2], bb0[0]);
                sa0[3] = hmul2u(afr[0][ks][3], bb1[0]);
                sa1[0] = hmul2u(afr[1][ks][0], bb0[1]);
                sa1[1] = hmul2u(afr[1][ks][1], bb1[1]);
                sa1[2] = hmul2u(afr[1][ks][2], bb0[1]);
                sa1[3] = hmul2u(afr[1][ks][3], bb1[1]);
                #pragma unroll
                for (int p = 0; p < 2; p++) {
                    uint32_t b[4];
                    uint32_t chunk = (uint32_t)(((ks << 1) | kh) ^ s_p[p]) << 4;
                    ldsm4(b, b_base[p] + kb_off + chunk);
                    MMA16816(acc[0][2 * p],     sa0[0], sa0[1], sa0[2], sa0[3], b[0], b[1]);
                    MMA16816(acc[1][2 * p],     sa1[0], sa1[1], sa1[2], sa1[3], b[0], b[1]);
                    MMA16816(acc[0][2 * p + 1], sa0[0], sa0[1], sa0[2], sa0[3], b[2], b[3]);
                    MMA16816(acc[1][2 * p + 1], sa1[0], sa1[1], sa1[2], sa1[3], b[2], b[3]);
                }
            }
        }

        // ---- store 32x32 warp tile as fp16 ----
        const int tid4 = lane & 3;
        #pragma unroll
        for (int mt = 0; mt < 2; mt++) {
            int t = t0 + rbase + mt * 16 + gid;
            #pragma unroll
            for (int nt = 0; nt < 4; nt++) {
                int col = warp_n * 32 + nt * 8 + tid4 * 2;
                if (t < T) {
                    __half2 h = __floats2half2_rn(acc[mt][nt][0], acc[mt][nt][1]);
                    *(__half2*)&g_contrib[(size_t)t * C_OUT + col] = h;
                }
                if (t + 8 < T) {
                    __half2 h = __floats2half2_rn(acc[mt][nt][2], acc[mt][nt][3]);
                    *(__half2*)&g_contrib[(size_t)(t + 8) * C_OUT + col] = h;
                }
            }
        }
        buf ^= 1;
    }
}

// ================= facet mean + bias + relu + fused BN stats =================
// Warp per facet; 2-facet unroll for MLP; prebn stored fp16.
__global__ void facet_kernel(const int* __restrict__ cnt,
                             const float* __restrict__ bias, int F) {
    __shared__ float ssum[64], ssq[64];
    int tid = threadIdx.x;
    if (tid < 64) { ssum[tid] = 0.0f; ssq[tid] = 0.0f; }
    __syncthreads();

    int gw   = (blockIdx.x * blockDim.x + tid) >> 5;
    int lane = tid & 31;
    int nw   = (gridDim.x * blockDim.x) >> 5;
    float b0 = bias[2 * lane];
    float b1 = bias[2 * lane + 1];
    float a0 = 0.0f, a1 = 0.0f, q0 = 0.0f, q1 = 0.0f;

    int f = 2 * gw;
    for (; f + 1 < F; f += 2 * nw) {
        int s0i = g_offs[f],     c0 = cnt[f];
        int s1i = g_offs[f + 1], c1 = cnt[f + 1];
        float x0 = 0.0f, x1 = 0.0f, y0 = 0.0f, y1 = 0.0f;
        int cmin = (c0 < c1) ? c0 : c1;
        int r = 0;
        for (; r < cmin; r++) {
            float2 u = __half22float2(((const __half2*)(g_contrib + (size_t)(s0i + r) * C_OUT))[lane]);
            float2 v = __half22float2(((const __half2*)(g_contrib + (size_t)(s1i + r) * C_OUT))[lane]);
            x0 += u.x; x1 += u.y;
            y0 += v.x; y1 += v.y;
        }
        for (; r < c0; r++) {
            float2 u = __half22float2(((const __half2*)(g_contrib + (size_t)(s0i + r) * C_OUT))[lane]);
            x0 += u.x; x1 += u.y;
        }
        for (; r < c1; r++) {
            float2 v = __half22float2(((const __half2*)(g_contrib + (size_t)(s1i + r) * C_OUT))[lane]);
            y0 += v.x; y1 += v.y;
        }
        float i0 = (c0 > 0) ? (1.0f / (float)c0) : 0.0f;
        float i1 = (c1 > 0) ? (1.0f / (float)c1) : 0.0f;
        float u0 = fmaxf(x0 * i0 + b0, 0.0f);
        float u1 = fmaxf(x1 * i0 + b1, 0.0f);
        float v0 = fmaxf(y0 * i1 + b0, 0.0f);
        float v1 = fmaxf(y1 * i1 + b1, 0.0f);
        *(__half2*)&g_prebn[(size_t)f * C_OUT + 2 * lane]       = __floats2half2_rn(u0, u1);
        *(__half2*)&g_prebn[(size_t)(f + 1) * C_OUT + 2 * lane] = __floats2half2_rn(v0, v1);
        a0 += u0 + v0; q0 += u0 * u0 + v0 * v0;
        a1 += u1 + v1; q1 += u1 * u1 + v1 * v1;
    }
    if (f < F) {   // tail facet
        int s0i = g_offs[f], c0 = cnt[f];
        float x0 = 0.0f, x1 = 0.0f;
        for (int r = 0; r < c0; r++) {
            float2 u = __half22float2(((const __half2*)(g_contrib + (size_t)(s0i + r) * C_OUT))[lane]);
            x0 += u.x; x1 += u.y;
        }
        float i0 = (c0 > 0) ? (1.0f / (float)c0) : 0.0f;
        float u0 = fmaxf(x0 * i0 + b0, 0.0f);
        float u1 = fmaxf(x1 * i0 + b1, 0.0f);
        *(__half2*)&g_prebn[(size_t)f * C_OUT + 2 * lane] = __floats2half2_rn(u0, u1);
        a0 += u0; q0 += u0 * u0;
        a1 += u1; q1 += u1 * u1;
    }
    atomicAdd(&ssum[2 * lane],     a0);
    atomicAdd(&ssq[2 * lane],      q0);
    atomicAdd(&ssum[2 * lane + 1], a1);
    atomicAdd(&ssq[2 * lane + 1],  q1);
    __syncthreads();
    if (tid < 64) {
        atomicAdd(&g_stats[tid],      ssum[tid]);
        atomicAdd(&g_stats[64 + tid], ssq[tid]);
    }
}

// ================= batchnorm apply (fp16 in, fp32 out) =================
__global__ void bn_kernel(const float* __restrict__ gamma,
                          const float* __restrict__ beta,
                          float* __restrict__ out, int F) {
    int idx = blockIdx.x * blockDim.x + threadIdx.x;   // 4-channel group index
    int total = F * (C_OUT / 4);
    float invF = 1.0f / (float)F;
    for (; idx < total; idx += gridDim.x * blockDim.x) {
        int o = (idx & 15) * 4;
        uint2 raw = *(const uint2*)&g_prebn[(size_t)idx * 4];
        float2 v01 = __half22float2(*(__half2*)&raw.x);
        float2 v23 = __half22float2(*(__half2*)&raw.y);
        float vv[4] = {v01.x, v01.y, v23.x, v23.y};
        float4 r;
        #pragma unroll
        for (int j = 0; j < 4; j++) {
            float mu  = g_stats[o + j] * invF;
            float var = g_stats[C_OUT + o + j] * invF - mu * mu;
            float sc  = rsqrtf(var + BN_EPS) * gamma[o + j];
            float bb  = beta[o + j];
            (&r.x)[j] = (vv[j] - mu) * sc + bb;
        }
        *(float4*)&out[(size_t)idx * 4] = r;
    }
}

// ================= launch =================
extern "C" void kernel_launch(void* const* d_in, const int* in_sizes, int n_in,
                              void* d_out, int out_size) {
    const float* X     = (const float*)d_in[0];
    const float* BARY  = (const float*)d_in[1];
    const float* W     = (const float*)d_in[2];
    const float* bias  = (const float*)d_in[3];
    const float* gamma = (const float*)d_in[4];
    const float* beta  = (const float*)d_in[5];
    const int*   cnt   = (const int*)d_in[6];

    int T = in_sizes[0] / C_IN;
    int F = in_sizes[6];
    int numTiles = (T + TILE_M - 1) / TILE_M;

    int sms = 148;
    cudaDeviceGetAttribute(&sms, cudaDevAttrMultiProcessorCount, 0);
    cudaFuncSetAttribute(gemm_mma_kernel, cudaFuncAttributeMaxDynamicSharedMemorySize, SMEM_GEMM);

    int nb = (F + 1023) / 1024;
    scan1_kernel<<<nb, 1024>>>(cnt, F);
    scan2_kernel<<<1, 1024>>>(nb);
    scan3_kernel<<<nb, 1024>>>(F);   // also zeroes g_stats

    gemm_mma_kernel<<<2 * sms, 256, SMEM_GEMM>>>(X, BARY, W, T, numTiles);

    facet_kernel<<<2048, 256>>>(cnt, bias, F);

    bn_kernel<<<2048, 256>>>(gamma, beta, (float*)d_out, F);
}

// round 11
// speedup vs baseline: 1.4396x; 1.2036x over previous
#include <cuda_runtime.h>
#include <cuda_fp16.h>
#include <math.h>
#include <stdint.h>

#define C_IN   64
#define C_OUT  64
#define NBASIS 9
#define TILE_M 128
#define MAX_T  1600000
#define MAX_F  400000
#define BN_EPS 1e-3f

// ---- scratch (device globals; no allocation allowed) ----
__device__ __half g_contrib[(size_t)MAX_T * C_OUT];  // fallback path only
__device__ __half g_prebn[(size_t)MAX_F * C_OUT];    // 51.2 MB (fp16)
__device__ int    g_offs[MAX_F];
__device__ int    g_blk[1024];
__device__ float  g_stats[2 * C_OUT];
__device__ int    g_flag;                             // 1 if all counts == 4

// ================= exclusive-scan of num_texture =================
__global__ void scan1_kernel(const int* __restrict__ cnt, int F) {
    __shared__ int s[1024];
    int tid = threadIdx.x;
    int f = blockIdx.x * 1024 + tid;
    int c = (f < F) ? cnt[f] : 0;
    s[tid] = c;
    __syncthreads();
    for (int off = 1; off < 1024; off <<= 1) {
        int v = (tid >= off) ? s[tid - off] : 0;
        __syncthreads();
        s[tid] += v;
        __syncthreads();
    }
    if (f < F) g_offs[f] = s[tid] - c;
    if (tid == 1023) g_blk[blockIdx.x] = s[1023];
}
__global__ void scan2_kernel(int nb) {
    __shared__ int s[1024];
    int tid = threadIdx.x;
    int c = (tid < nb) ? g_blk[tid] : 0;
    s[tid] = c;
    __syncthreads();
    for (int off = 1; off < 1024; off <<= 1) {
        int v = (tid >= off) ? s[tid - off] : 0;
        __syncthreads();
        s[tid] += v;
        __syncthreads();
    }
    if (tid < nb) g_blk[tid] = s[tid] - c;
    if (tid == 0) g_flag = 1;
}
__global__ void scan3_kernel(const int* __restrict__ cnt, int F) {
    int f = blockIdx.x * 1024 + threadIdx.x;
    bool ok = true;
    if (f < F) {
        g_offs[f] += g_blk[blockIdx.x];
        ok = (cnt[f] == 4);
    }
    if (blockIdx.x == 0 && threadIdx.x < 2 * C_OUT) g_stats[threadIdx.x] = 0.0f;
    if (!__syncthreads_and(ok ? 1 : 0)) {
        if (threadIdx.x == 0) g_flag = 0;
    }
}

// ================= mma.sync GEMM with fused facet epilogue =================
// contrib[t,o] = sum_k ( (x[t,:] * bary[t,k]) fp16 ) @ W_k[o,:]^T
// flag path: facet = 4 consecutive textures -> mean+bias+relu fused, writes prebn.
//
// SMEM per CTA (97168 B -> two CTAs per SM):
//   Wh   : [kb*64+o] rows of 128 B, XOR-swizzled 16B chunks  = 73728 B
//   Ax   : [t] rows, pad-72 halfs (144 B)  (reused for acc)  = 18432 B
//   Bsh  : 2 x [kb*132 + t] fp16                             =  4752 B
//   Bias : 64 fp32                                           =   256 B
#define SM_W      0
#define SM_AX     73728
#define SM_BS     92160
#define BS_HALFS  1188            // 9 * 132
#define SM_BIAS   96912
#define SMEM_GEMM 97168

#define MMA16816(d, a0, a1, a2, a3, b0, b1)                                 \
    asm volatile(                                                           \
        "mma.sync.aligned.m16n8k16.row.col.f32.f16.f16.f32 "                \
        "{%0,%1,%2,%3},{%4,%5,%6,%7},{%8,%9},{%0,%1,%2,%3};"                \
        : "+f"((d)[0]), "+f"((d)[1]), "+f"((d)[2]), "+f"((d)[3])            \
        : "r"(a0), "r"(a1), "r"(a2), "r"(a3), "r"(b0), "r"(b1))

__device__ __forceinline__ void ldsm4(uint32_t* r, uint32_t addr) {
    asm volatile("ldmatrix.sync.aligned.m8n8.x4.shared.b16 {%0,%1,%2,%3}, [%4];"
                 : "=r"(r[0]), "=r"(r[1]), "=r"(r[2]), "=r"(r[3]) : "r"(addr));
}
__device__ __forceinline__ uint32_t hmul2u(uint32_t a, uint32_t b) {
    __half2 r = __hmul2(*(__half2*)&a, *(__half2*)&b);
    return *(uint32_t*)&r;
}

__global__ void __launch_bounds__(256, 2) gemm_mma_kernel(
    const float* __restrict__ X,     // [T, 64]
    const float* __restrict__ BARY,  // [T, 9]
    const float* __restrict__ W,     // [64, 64, 9]  (o, i, k)
    const float* __restrict__ BIAS,  // [64]
    int T, int F, int numTiles)
{
    extern __shared__ char sm[];
    const uint32_t smb = (uint32_t)__cvta_generic_to_shared(sm);
    __half* Bsh = (__half*)(sm + SM_BS);

    const int tid  = threadIdx.x;
    const int wid  = tid >> 5;
    const int lane = tid & 31;
    const int gid  = lane >> 2;
    const int tid4 = lane & 3;
    const int warp_m = wid >> 1;     // 0..3
    const int warp_n = wid & 1;      // 0..1
    const int rbase  = warp_m * 32;

    const int flag = g_flag;

    // ---- convert W once: swizzled rows [kb*64+o][i], 128B rows; bias ----
    for (int idx = tid; idx < C_OUT * C_IN * NBASIS; idx += 256) {
        int o   = idx / (C_IN * NBASIS);
        int rem = idx - o * (C_IN * NBASIS);
        int i   = rem / NBASIS;
        int k   = rem - i * NBASIS;
        uint32_t byte = (uint32_t)(k * 64 + o) * 128
                      + ((((uint32_t)i >> 3) ^ (uint32_t)(o & 7)) << 4)
                      + (i & 7) * 2;
        *(__half*)(sm + byte) = __float2half_rn(W[idx]);
    }
    if (tid < 64) ((float*)(sm + SM_BIAS))[tid] = BIAS[tid];

    // ---- per-thread LDSM addresses ----
    uint32_t a_base[2];
    #pragma unroll
    for (int mt = 0; mt < 2; mt++)
        a_base[mt] = smb + SM_AX
                   + (uint32_t)(rbase + mt * 16 + (lane & 15)) * 144
                   + ((lane >> 4) << 4);
    uint32_t b_base[2];
    int s_p[2];
    const int kh = (lane >> 3) & 1;
    #pragma unroll
    for (int p = 0; p < 2; p++) {
        int n_local = warp_n * 32 + p * 16 + ((lane >> 4) & 1) * 8 + (lane & 7);
        b_base[p] = smb + SM_W + (uint32_t)n_local * 128;
        s_p[p] = n_local & 7;
    }

    // ---- X prefetch mapping (coalesced: each LDG.128 covers 512B contig) ----
    const int hl   = lane >> 4;          // 0/1
    const int lidx = lane & 15;          // 16B chunk within 256B row
    // thread's j-th chunk: row = wid*16 + 2j + hl, floats [lidx*4, lidx*4+4)
    // ---- bary prefetch mapping ----
    const int prow = tid >> 1;
    const int phf  = tid & 1;
    const int kb0  = phf ? 5 : 0;
    const int nby  = phf ? 4 : 5;

    uint32_t pk[16];
    float    by[5];

    int tile = blockIdx.x;
    {   // prologue prefetch
        #pragma unroll
        for (int j = 0; j < 8; j++) {
            int t = tile * TILE_M + wid * 16 + 2 * j + hl;
            if (t < T) {
                float4 v = *(const float4*)(X + (size_t)t * C_IN + lidx * 4);
                __half2 h0 = __floats2half2_rn(v.x, v.y);
                __half2 h1 = __floats2half2_rn(v.z, v.w);
                pk[2 * j]     = *(uint32_t*)&h0;
                pk[2 * j + 1] = *(uint32_t*)&h1;
            } else { pk[2 * j] = 0u; pk[2 * j + 1] = 0u; }
        }
        int t = tile * TILE_M + prow;
        #pragma unroll
        for (int j = 0; j < 5; j++) {
            by[j] = 0.0f;
            if (j < nby && t < T) by[j] = BARY[(size_t)t * NBASIS + kb0 + j];
        }
    }
    __syncthreads();   // W + bias ready

    int buf = 0;
    for (; tile < numTiles; tile += gridDim.x) {
        const int t0 = tile * TILE_M;

        // ---- store phase: regs -> SMEM ----
        {
            #pragma unroll
            for (int j = 0; j < 8; j++) {
                int rowg = wid * 16 + 2 * j + hl;
                *(uint2*)(sm + SM_AX + rowg * 144 + lidx * 8) =
                    make_uint2(pk[2 * j], pk[2 * j + 1]);
            }
            __half* BsB = Bsh + buf * BS_HALFS;
            #pragma unroll
            for (int j = 0; j < 5; j++)
                if (j < nby) BsB[(kb0 + j) * 132 + prow] = __float2half_rn(by[j]);
        }
        __syncthreads();   // barrier A: stores visible

        // ---- load A fragments ONCE per tile ----
        uint32_t afr[2][4][4];
        #pragma unroll
        for (int mt = 0; mt < 2; mt++)
            #pragma unroll
            for (int ks = 0; ks < 4; ks++)
                ldsm4(afr[mt][ks], a_base[mt] + ks * 32);
        __syncthreads();   // barrier B: Ax free

        // ---- prefetch next tile (hidden under MMA) ----
        {
            int ntile = tile + gridDim.x;
            if (ntile < numTiles) {
                #pragma unroll
                for (int j = 0; j < 8; j++) {
                    int t = ntile * TILE_M + wid * 16 + 2 * j + hl;
                    if (t < T) {
                        float4 v = *(const float4*)(X + (size_t)t * C_IN + lidx * 4);
                        __half2 h0 = __floats2half2_rn(v.x, v.y);
                        __half2 h1 = __floats2half2_rn(v.z, v.w);
                        pk[2 * j]     = *(uint32_t*)&h0;
                        pk[2 * j + 1] = *(uint32_t*)&h1;
                    } else { pk[2 * j] = 0u; pk[2 * j + 1] = 0u; }
                }
                int t = ntile * TILE_M + prow;
                #pragma unroll
                for (int j = 0; j < 5; j++) {
                    by[j] = 0.0f;
                    if (j < nby && t < T) by[j] = BARY[(size_t)t * NBASIS + kb0 + j];
                }
            }
        }

        const __half* BsB = Bsh + buf * BS_HALFS;

        float acc[2][4][4];
        #pragma unroll
        for (int mt = 0; mt < 2; mt++)
            #pragma unroll
            for (int nt = 0; nt < 4; nt++)
                #pragma unroll
                for (int e = 0; e < 4; e++) acc[mt][nt][e] = 0.0f;

        #pragma unroll 1
        for (int kb = 0; kb < NBASIS; kb++) {
            uint32_t bb0[2], bb1[2];
            #pragma unroll
            for (int mt = 0; mt < 2; mt++) {
                int r = rbase + mt * 16 + gid;
                __half2 h0 = __half2half2(BsB[kb * 132 + r]);
                __half2 h1 = __half2half2(BsB[kb * 132 + r + 8]);
                bb0[mt] = *(uint32_t*)&h0;
                bb1[mt] = *(uint32_t*)&h1;
            }
            const uint32_t kb_off = (uint32_t)kb * 8192;
            #pragma unroll
            for (int ks = 0; ks < 4; ks++) {
                uint32_t sa0[4], sa1[4];
                sa0[0] = hmul2u(afr[0][ks][0], bb0[0]);
                sa0[1] = hmul2u(afr[0][ks][1], bb1[0]);
                sa0[2] = hmul2u(afr[0][ks][2], bb0[0]);
                sa0[3] = hmul2u(afr[0][ks][3], bb1[0]);
                sa1[0] = hmul2u(afr[1][ks][0], bb0[1]);
                sa1[1] = hmul2u(afr[1][ks][1], bb1[1]);
                sa1[2] = hmul2u(afr[1][ks][2], bb0[1]);
                sa1[3] = hmul2u(afr[1][ks][3], bb1[1]);
                #pragma unroll
                for (int p = 0; p < 2; p++) {
                    uint32_t b[4];
                    uint32_t chunk = (uint32_t)(((ks << 1) | kh) ^ s_p[p]) << 4;
                    ldsm4(b, b_base[p] + kb_off + chunk);
                    MMA16816(acc[0][2 * p],     sa0[0], sa0[1], sa0[2], sa0[3], b[0], b[1]);
                    MMA16816(acc[1][2 * p],     sa1[0], sa1[1], sa1[2], sa1[3], b[0], b[1]);
                    MMA16816(acc[0][2 * p + 1], sa0[0], sa0[1], sa0[2], sa0[3], b[2], b[3]);
                    MMA16816(acc[1][2 * p + 1], sa1[0], sa1[1], sa1[2], sa1[3], b[2], b[3]);
                }
            }
        }

        if (flag) {
            // ---- fused facet epilogue: stage acc fp16 into Ax (dead) ----
            #pragma unroll
            for (int mt = 0; mt < 2; mt++) {
                int rlo = rbase + mt * 16 + gid;
                #pragma unroll
                for (int nt = 0; nt < 4; nt++) {
                    int colb = (warp_n * 32 + nt * 8 + tid4 * 2) * 2;
                    *(__half2*)(sm + SM_AX + rlo * 144 + colb) =
                        __floats2half2_rn(acc[mt][nt][0], acc[mt][nt][1]);
                    *(__half2*)(sm + SM_AX + (rlo + 8) * 144 + colb) =
                        __floats2half2_rn(acc[mt][nt][2], acc[mt][nt][3]);
                }
            }
            __syncthreads();   // barrier C: acc staged

            // thread -> (facet fo = tid>>3, col group cg = tid&7 of 8 cols)
            int fo = tid >> 3, cg = tid & 7;
            const char* rp = sm + SM_AX + (fo * 4) * 144 + cg * 16;
            float s[8] = {0, 0, 0, 0, 0, 0, 0, 0};
            #pragma unroll
            for (int r = 0; r < 4; r++) {
                uint4 u = *(const uint4*)(rp + r * 144);
                float2 a0 = __half22float2(*(__half2*)&u.x);
                float2 a1 = __half22float2(*(__half2*)&u.y);
                float2 a2 = __half22float2(*(__half2*)&u.z);
                float2 a3 = __half22float2(*(__half2*)&u.w);
                s[0] += a0.x; s[1] += a0.y; s[2] += a1.x; s[3] += a1.y;
                s[4] += a2.x; s[5] += a2.y; s[6] += a3.x; s[7] += a3.y;
            }
            int fg = (t0 >> 2) + fo;
            if (fg < F) {
                const float* bb = (const float*)(sm + SM_BIAS) + cg * 8;
                uint4 outv;
                __half2* ov = (__half2*)&outv;
                #pragma unroll
                for (int j = 0; j < 4; j++) {
                    float v0 = fmaxf(s[2 * j] * 0.25f + bb[2 * j], 0.0f);
                    float v1 = fmaxf(s[2 * j + 1] * 0.25f + bb[2 * j + 1], 0.0f);
                    ov[j] = __floats2half2_rn(v0, v1);
                }
                *(uint4*)&g_prebn[(size_t)fg * C_OUT + cg * 8] = outv;
            }
            __syncthreads();   // barrier D: reduce reads done before next Ax store
        } else {
            // ---- fallback: scattered contrib store ----
            #pragma unroll
            for (int mt = 0; mt < 2; mt++) {
                int t = t0 + rbase + mt * 16 + gid;
                #pragma unroll
                for (int nt = 0; nt < 4; nt++) {
                    int col = warp_n * 32 + nt * 8 + tid4 * 2;
                    if (t < T)
                        *(__half2*)&g_contrib[(size_t)t * C_OUT + col] =
                            __floats2half2_rn(acc[mt][nt][0], acc[mt][nt][1]);
                    if (t + 8 < T)
                        *(__half2*)&g_contrib[(size_t)(t + 8) * C_OUT + col] =
                            __floats2half2_rn(acc[mt][nt][2], acc[mt][nt][3]);
                }
            }
        }
        buf ^= 1;
    }
}

// ================= facet fallback (general counts; early-exit on flag) ======
__global__ void facet_kernel(const int* __restrict__ cnt,
                             const float* __restrict__ bias, int F) {
    if (g_flag) return;
    int tid  = threadIdx.x;
    int gw   = (blockIdx.x * blockDim.x + tid) >> 5;
    int lane = tid & 31;
    int nw   = (gridDim.x * blockDim.x) >> 5;
    float b0 = bias[2 * lane];
    float b1 = bias[2 * lane + 1];
    for (int f = gw; f < F; f += nw) {
        int start = g_offs[f];
        int c = cnt[f];
        float s0 = 0.0f, s1 = 0.0f;
        for (int r = 0; r < c; r++) {
            float2 u = __half22float2(((const __half2*)(g_contrib + (size_t)(start + r) * C_OUT))[lane]);
            s0 += u.x; s1 += u.y;
        }
        float inv = (c > 0) ? (1.0f / (float)c) : 0.0f;
        float v0 = fmaxf(s0 * inv + b0, 0.0f);
        float v1 = fmaxf(s1 * inv + b1, 0.0f);
        *(__half2*)&g_prebn[(size_t)f * C_OUT + 2 * lane] = __floats2half2_rn(v0, v1);
    }
}

// ================= BN stats over prebn =================
__global__ void stats_kernel(int F) {
    __shared__ float ssum[64], ssq[64];
    int tid = threadIdx.x;
    if (tid < 64) { ssum[tid] = 0.0f; ssq[tid] = 0.0f; }
    __syncthreads();

    int cp = tid & 31;                 // half2 column pair (fixed per thread)
    float s0 = 0, s1 = 0, q0 = 0, q1 = 0;
    int idx = blockIdx.x * blockDim.x + tid;
    int total = F * 32;
    int stride = gridDim.x * blockDim.x;
    for (; idx < total; idx += stride) {
        float2 v = __half22float2(((const __half2*)g_prebn)[idx]);
        s0 += v.x; s1 += v.y;
        q0 += v.x * v.x; q1 += v.y * v.y;
    }
    atomicAdd(&ssum[2 * cp], s0); atomicAdd(&ssum[2 * cp + 1], s1);
    atomicAdd(&ssq[2 * cp],  q0); atomicAdd(&ssq[2 * cp + 1],  q1);
    __syncthreads();
    if (tid < 64) {
        atomicAdd(&g_stats[tid],      ssum[tid]);
        atomicAdd(&g_stats[64 + tid], ssq[tid]);
    }
}

// ================= batchnorm apply (fp16 in, fp32 out) =================
__global__ void bn_kernel(const float* __restrict__ gamma,
                          const float* __restrict__ beta,
                          float* __restrict__ out, int F) {
    int idx = blockIdx.x * blockDim.x + threadIdx.x;
    int total = F * (C_OUT / 4);
    float invF = 1.0f / (float)F;
    for (; idx < total; idx += gridDim.x * blockDim.x) {
        int o = (idx & 15) * 4;
        uint2 raw = *(const uint2*)&g_prebn[(size_t)idx * 4];
        float2 v01 = __half22float2(*(__half2*)&raw.x);
        float2 v23 = __half22float2(*(__half2*)&raw.y);
        float vv[4] = {v01.x, v01.y, v23.x, v23.y};
        float4 r;
        #pragma unroll
        for (int j = 0; j < 4; j++) {
            float mu  = g_stats[o + j] * invF;
            float var = g_stats[C_OUT + o + j] * invF - mu * mu;
            float sc  = rsqrtf(var + BN_EPS) * gamma[o + j];
            float bb  = beta[o + j];
            (&r.x)[j] = (vv[j] - mu) * sc + bb;
        }
        *(float4*)&out[(size_t)idx * 4] = r;
    }
}

// ================= launch =================
extern "C" void kernel_launch(void* const* d_in, const int* in_sizes, int n_in,
                              void* d_out, int out_size) {
    const float* X     = (const float*)d_in[0];
    const float* BARY  = (const float*)d_in[1];
    const float* W     = (const float*)d_in[2];
    const float* bias  = (const float*)d_in[3];
    const float* gamma = (const float*)d_in[4];
    const float* beta  = (const float*)d_in[5];
    const int*   cnt   = (const int*)d_in[6];

    int T = in_sizes[0] / C_IN;
    int F = in_sizes[6];
    int numTiles = (T + TILE_M - 1) / TILE_M;

    int sms = 148;
    cudaDeviceGetAttribute(&sms, cudaDevAttrMultiProcessorCount, 0);
    cudaFuncSetAttribute(gemm_mma_kernel, cudaFuncAttributeMaxDynamicSharedMemorySize, SMEM_GEMM);

    int nb = (F + 1023) / 1024;
    scan1_kernel<<<nb, 1024>>>(cnt, F);
    scan2_kernel<<<1, 1024>>>(nb);
    scan3_kernel<<<nb, 1024>>>(cnt, F);   // offsets + flag + zero stats

    gemm_mma_kernel<<<2 * sms, 256, SMEM_GEMM>>>(X, BARY, W, bias, T, F, numTiles);

    facet_kernel<<<2048, 256>>>(cnt, bias, F);   // early-exits when flag==1

    stats_kernel<<<512, 256>>>(F);
    bn_kernel<<<2048, 256>>>(gamma, beta, (float*)d_out, F);
}

// round 12
// speedup vs baseline: 1.4846x; 1.0312x over previous
#include <cuda_runtime.h>
#include <cuda_fp16.h>
#include <math.h>
#include <stdint.h>

#define C_IN   64
#define C_OUT  64
#define NBASIS 9
#define TILE_M 128
#define MAX_T  1600000
#define MAX_F  400000
#define BN_EPS 1e-3f

// ---- scratch (device globals; no allocation allowed) ----
__device__ __half g_contrib[(size_t)MAX_T * C_OUT];  // fallback path only
__device__ __half g_prebn[(size_t)MAX_F * C_OUT];    // 51.2 MB (fp16)
__device__ int    g_offs[MAX_F];
__device__ int    g_blk[1024];
__device__ float  g_stats[2 * C_OUT];
__device__ int    g_flag;                             // 1 if all counts == 4

// ================= exclusive-scan of num_texture =================
__global__ void scan1_kernel(const int* __restrict__ cnt, int F) {
    __shared__ int s[1024];
    int tid = threadIdx.x;
    int f = blockIdx.x * 1024 + tid;
    int c = (f < F) ? cnt[f] : 0;
    s[tid] = c;
    __syncthreads();
    for (int off = 1; off < 1024; off <<= 1) {
        int v = (tid >= off) ? s[tid - off] : 0;
        __syncthreads();
        s[tid] += v;
        __syncthreads();
    }
    if (f < F) g_offs[f] = s[tid] - c;
    if (tid == 1023) g_blk[blockIdx.x] = s[1023];
}
__global__ void scan2_kernel(int nb) {
    __shared__ int s[1024];
    int tid = threadIdx.x;
    int c = (tid < nb) ? g_blk[tid] : 0;
    s[tid] = c;
    __syncthreads();
    for (int off = 1; off < 1024; off <<= 1) {
        int v = (tid >= off) ? s[tid - off] : 0;
        __syncthreads();
        s[tid] += v;
        __syncthreads();
    }
    if (tid < nb) g_blk[tid] = s[tid] - c;
    if (tid == 0) g_flag = 1;
}
__global__ void scan3_kernel(const int* __restrict__ cnt, int F) {
    int f = blockIdx.x * 1024 + threadIdx.x;
    bool ok = true;
    if (f < F) {
        g_offs[f] += g_blk[blockIdx.x];
        ok = (cnt[f] == 4);
    }
    if (blockIdx.x == 0 && threadIdx.x < 2 * C_OUT) g_stats[threadIdx.x] = 0.0f;
    if (!__syncthreads_and(ok ? 1 : 0)) {
        if (threadIdx.x == 0) g_flag = 0;
    }
}

// ================= mma.sync GEMM with shuffle-fused facet epilogue =========
// contrib[t,o] = sum_k ( (x[t,:] * bary[t,k]) fp16 ) @ W_k[o,:]^T
// flag path: facet = 4 consecutive textures -> butterfly-shuffle sum in regs,
// mean+bias+relu, direct prebn write. No staging, no barriers C/D.
//
// SMEM per CTA (97168 B -> two CTAs per SM):
//   Wh   : [kb*64+o] rows of 128 B, XOR-swizzled 16B chunks  = 73728 B
//   Ax   : [t] rows, pad-72 halfs (144 B)                    = 18432 B
//   Bsh  : 2 x [kb*132 + t] fp16                             =  4752 B
//   Bias : 64 fp32                                           =   256 B
#define SM_W      0
#define SM_AX     73728
#define SM_BS     92160
#define BS_HALFS  1188            // 9 * 132
#define SM_BIAS   96912
#define SMEM_GEMM 97168

#define MMA16816(d, a0, a1, a2, a3, b0, b1)                                 \
    asm volatile(                                                           \
        "mma.sync.aligned.m16n8k16.row.col.f32.f16.f16.f32 "                \
        "{%0,%1,%2,%3},{%4,%5,%6,%7},{%8,%9},{%0,%1,%2,%3};"                \
        : "+f"((d)[0]), "+f"((d)[1]), "+f"((d)[2]), "+f"((d)[3])            \
        : "r"(a0), "r"(a1), "r"(a2), "r"(a3), "r"(b0), "r"(b1))

__device__ __forceinline__ void ldsm4(uint32_t* r, uint32_t addr) {
    asm volatile("ldmatrix.sync.aligned.m8n8.x4.shared.b16 {%0,%1,%2,%3}, [%4];"
                 : "=r"(r[0]), "=r"(r[1]), "=r"(r[2]), "=r"(r[3]) : "r"(addr));
}
__device__ __forceinline__ uint32_t hmul2u(uint32_t a, uint32_t b) {
    __half2 r = __hmul2(*(__half2*)&a, *(__half2*)&b);
    return *(uint32_t*)&r;
}
__device__ __forceinline__ uint32_t hadd2u(uint32_t a, uint32_t b) {
    __half2 r = __hadd2(*(__half2*)&a, *(__half2*)&b);
    return *(uint32_t*)&r;
}

__global__ void __launch_bounds__(256, 2) gemm_mma_kernel(
    const float* __restrict__ X,     // [T, 64]
    const float* __restrict__ BARY,  // [T, 9]
    const float* __restrict__ W,     // [64, 64, 9]  (o, i, k)
    const float* __restrict__ BIAS,  // [64]
    int T, int F, int numTiles)
{
    extern __shared__ char sm[];
    const uint32_t smb = (uint32_t)__cvta_generic_to_shared(sm);
    __half* Bsh = (__half*)(sm + SM_BS);

    const int tid  = threadIdx.x;
    const int wid  = tid >> 5;
    const int lane = tid & 31;
    const int gid  = lane >> 2;
    const int tid4 = lane & 3;
    const int warp_m = wid >> 1;     // 0..3
    const int warp_n = wid & 1;      // 0..1
    const int rbase  = warp_m * 32;

    const int flag = g_flag;

    // ---- convert W once: swizzled rows [kb*64+o][i], 128B rows; bias ----
    for (int idx = tid; idx < C_OUT * C_IN * NBASIS; idx += 256) {
        int o   = idx / (C_IN * NBASIS);
        int rem = idx - o * (C_IN * NBASIS);
        int i   = rem / NBASIS;
        int k   = rem - i * NBASIS;
        uint32_t byte = (uint32_t)(k * 64 + o) * 128
                      + ((((uint32_t)i >> 3) ^ (uint32_t)(o & 7)) << 4)
                      + (i & 7) * 2;
        *(__half*)(sm + byte) = __float2half_rn(W[idx]);
    }
    if (tid < 64) ((float*)(sm + SM_BIAS))[tid] = BIAS[tid];

    // ---- per-thread LDSM addresses ----
    uint32_t a_base[2];
    #pragma unroll
    for (int mt = 0; mt < 2; mt++)
        a_base[mt] = smb + SM_AX
                   + (uint32_t)(rbase + mt * 16 + (lane & 15)) * 144
                   + ((lane >> 4) << 4);
    uint32_t b_base[2];
    int s_p[2];
    const int kh = (lane >> 3) & 1;
    #pragma unroll
    for (int p = 0; p < 2; p++) {
        int n_local = warp_n * 32 + p * 16 + ((lane >> 4) & 1) * 8 + (lane & 7);
        b_base[p] = smb + SM_W + (uint32_t)n_local * 128;
        s_p[p] = n_local & 7;
    }

    // ---- X prefetch mapping (coalesced LDG.128: 512B contig per chunk) ----
    const int hl   = lane >> 4;          // 0/1
    const int lidx = lane & 15;          // 16B chunk within 256B row
    // ---- bary prefetch mapping ----
    const int prow = tid >> 1;
    const int phf  = tid & 1;
    const int kb0  = phf ? 5 : 0;
    const int nby  = phf ? 4 : 5;

    uint32_t pk[16];
    float    by[5];

    int tile = blockIdx.x;
    {   // prologue prefetch
        #pragma unroll
        for (int j = 0; j < 8; j++) {
            int t = tile * TILE_M + wid * 16 + 2 * j + hl;
            if (t < T) {
                float4 v = *(const float4*)(X + (size_t)t * C_IN + lidx * 4);
                __half2 h0 = __floats2half2_rn(v.x, v.y);
                __half2 h1 = __floats2half2_rn(v.z, v.w);
                pk[2 * j]     = *(uint32_t*)&h0;
                pk[2 * j + 1] = *(uint32_t*)&h1;
            } else { pk[2 * j] = 0u; pk[2 * j + 1] = 0u; }
        }
        int t = tile * TILE_M + prow;
        #pragma unroll
        for (int j = 0; j < 5; j++) {
            by[j] = 0.0f;
            if (j < nby && t < T) by[j] = BARY[(size_t)t * NBASIS + kb0 + j];
        }
    }
    __syncthreads();   // W + bias ready

    int buf = 0;
    for (; tile < numTiles; tile += gridDim.x) {
        const int t0 = tile * TILE_M;

        // ---- store phase: regs -> SMEM ----
        {
            #pragma unroll
            for (int j = 0; j < 8; j++) {
                int rowg = wid * 16 + 2 * j + hl;
                *(uint2*)(sm + SM_AX + rowg * 144 + lidx * 8) =
                    make_uint2(pk[2 * j], pk[2 * j + 1]);
            }
            __half* BsB = Bsh + buf * BS_HALFS;
            #pragma unroll
            for (int j = 0; j < 5; j++)
                if (j < nby) BsB[(kb0 + j) * 132 + prow] = __float2half_rn(by[j]);
        }
        __syncthreads();   // barrier A: stores visible

        // ---- load A fragments ONCE per tile ----
        uint32_t afr[2][4][4];
        #pragma unroll
        for (int mt = 0; mt < 2; mt++)
            #pragma unroll
            for (int ks = 0; ks < 4; ks++)
                ldsm4(afr[mt][ks], a_base[mt] + ks * 32);
        __syncthreads();   // barrier B: Ax free

        // ---- prefetch next tile (hidden under MMA) ----
        {
            int ntile = tile + gridDim.x;
            if (ntile < numTiles) {
                #pragma unroll
                for (int j = 0; j < 8; j++) {
                    int t = ntile * TILE_M + wid * 16 + 2 * j + hl;
                    if (t < T) {
                        float4 v = *(const float4*)(X + (size_t)t * C_IN + lidx * 4);
                        __half2 h0 = __floats2half2_rn(v.x, v.y);
                        __half2 h1 = __floats2half2_rn(v.z, v.w);
                        pk[2 * j]     = *(uint32_t*)&h0;
                        pk[2 * j + 1] = *(uint32_t*)&h1;
                    } else { pk[2 * j] = 0u; pk[2 * j + 1] = 0u; }
                }
                int t = ntile * TILE_M + prow;
                #pragma unroll
                for (int j = 0; j < 5; j++) {
                    by[j] = 0.0f;
                    if (j < nby && t < T) by[j] = BARY[(size_t)t * NBASIS + kb0 + j];
                }
            }
        }

        const __half* BsB = Bsh + buf * BS_HALFS;

        float acc[2][4][4];
        #pragma unroll
        for (int mt = 0; mt < 2; mt++)
            #pragma unroll
            for (int nt = 0; nt < 4; nt++)
                #pragma unroll
                for (int e = 0; e < 4; e++) acc[mt][nt][e] = 0.0f;

        #pragma unroll 1
        for (int kb = 0; kb < NBASIS; kb++) {
            uint32_t bb0[2], bb1[2];
            #pragma unroll
            for (int mt = 0; mt < 2; mt++) {
                int r = rbase + mt * 16 + gid;
                __half2 h0 = __half2half2(BsB[kb * 132 + r]);
                __half2 h1 = __half2half2(BsB[kb * 132 + r + 8]);
                bb0[mt] = *(uint32_t*)&h0;
                bb1[mt] = *(uint32_t*)&h1;
            }
            const uint32_t kb_off = (uint32_t)kb * 8192;
            #pragma unroll
            for (int ks = 0; ks < 4; ks++) {
                uint32_t sa0[4], sa1[4];
                sa0[0] = hmul2u(afr[0][ks][0], bb0[0]);
                sa0[1] = hmul2u(afr[0][ks][1], bb1[0]);
                sa0[2] = hmul2u(afr[0][ks][2], bb0[0]);
                sa0[3] = hmul2u(afr[0][ks][3], bb1[0]);
                sa1[0] = hmul2u(afr[1][ks][0], bb0[1]);
                sa1[1] = hmul2u(afr[1][ks][1], bb1[1]);
                sa1[2] = hmul2u(afr[1][ks][2], bb0[1]);
                sa1[3] = hmul2u(afr[1][ks][3], bb1[1]);
                #pragma unroll
                for (int p = 0; p < 2; p++) {
                    uint32_t b[4];
                    uint32_t chunk = (uint32_t)(((ks << 1) | kh) ^ s_p[p]) << 4;
                    ldsm4(b, b_base[p] + kb_off + chunk);
                    MMA16816(acc[0][2 * p],     sa0[0], sa0[1], sa0[2], sa0[3], b[0], b[1]);
                    MMA16816(acc[1][2 * p],     sa1[0], sa1[1], sa1[2], sa1[3], b[0], b[1]);
                    MMA16816(acc[0][2 * p + 1], sa0[0], sa0[1], sa0[2], sa0[3], b[2], b[3]);
                    MMA16816(acc[1][2 * p + 1], sa1[0], sa1[1], sa1[2], sa1[3], b[2], b[3]);
                }
            }
        }

        if (flag) {
            // ---- shuffle-fused facet epilogue (no barriers, no staging) ----
            // pack col-pairs to half2: hp[mt][nt][half]
            uint32_t hp[2][4][2];
            #pragma unroll
            for (int mt = 0; mt < 2; mt++)
                #pragma unroll
                for (int nt = 0; nt < 4; nt++) {
                    __half2 lo = __floats2half2_rn(acc[mt][nt][0], acc[mt][nt][1]);
                    __half2 hi = __floats2half2_rn(acc[mt][nt][2], acc[mt][nt][3]);
                    hp[mt][nt][0] = *(uint32_t*)&lo;
                    hp[mt][nt][1] = *(uint32_t*)&hi;
                }
            // butterfly over lane bits 2,3 (sums the 4 rows of each facet)
            #pragma unroll
            for (int mt = 0; mt < 2; mt++)
                #pragma unroll
                for (int nt = 0; nt < 4; nt++)
                    #pragma unroll
                    for (int h = 0; h < 2; h++) {
                        uint32_t v = hp[mt][nt][h];
                        v = hadd2u(v, __shfl_xor_sync(0xFFFFFFFF, v, 4));
                        v = hadd2u(v, __shfl_xor_sync(0xFFFFFFFF, v, 8));
                        hp[mt][nt][h] = v;
                    }
            if ((lane & 12) == 0) {
                int g1 = lane >> 4;
                int fbase = (t0 >> 2) + warp_m * 8 + g1;
                #pragma unroll
                for (int nt = 0; nt < 4; nt++) {
                    int col = warp_n * 32 + nt * 8 + tid4 * 2;
                    float2 bb = *(const float2*)((const float*)(sm + SM_BIAS) + col);
                    #pragma unroll
                    for (int mt = 0; mt < 2; mt++)
                        #pragma unroll
                        for (int h = 0; h < 2; h++) {
                            int fg = fbase + mt * 4 + h * 2;
                            if (fg < F) {
                                float2 s = __half22float2(*(__half2*)&hp[mt][nt][h]);
                                float v0 = fmaxf(s.x * 0.25f + bb.x, 0.0f);
                                float v1 = fmaxf(s.y * 0.25f + bb.y, 0.0f);
                                *(__half2*)&g_prebn[(size_t)fg * C_OUT + col] =
                                    __floats2half2_rn(v0, v1);
                            }
                        }
                }
            }
        } else {
            // ---- fallback: scattered contrib store ----
            #pragma unroll
            for (int mt = 0; mt < 2; mt++) {
                int t = t0 + rbase + mt * 16 + gid;
                #pragma unroll
                for (int nt = 0; nt < 4; nt++) {
                    int col = warp_n * 32 + nt * 8 + tid4 * 2;
                    if (t < T)
                        *(__half2*)&g_contrib[(size_t)t * C_OUT + col] =
                            __floats2half2_rn(acc[mt][nt][0], acc[mt][nt][1]);
                    if (t + 8 < T)
                        *(__half2*)&g_contrib[(size_t)(t + 8) * C_OUT + col] =
                            __floats2half2_rn(acc[mt][nt][2], acc[mt][nt][3]);
                }
            }
        }
        buf ^= 1;
    }
}

// ================= facet fallback (general counts; early-exit on flag) ======
__global__ void facet_kernel(const int* __restrict__ cnt,
                             const float* __restrict__ bias, int F) {
    if (g_flag) return;
    int tid  = threadIdx.x;
    int gw   = (blockIdx.x * blockDim.x + tid) >> 5;
    int lane = tid & 31;
    int nw   = (gridDim.x * blockDim.x) >> 5;
    float b0 = bias[2 * lane];
    float b1 = bias[2 * lane + 1];
    for (int f = gw; f < F; f += nw) {
        int start = g_offs[f];
        int c = cnt[f];
        float s0 = 0.0f, s1 = 0.0f;
        for (int r = 0; r < c; r++) {
            float2 u = __half22float2(((const __half2*)(g_contrib + (size_t)(start + r) * C_OUT))[lane]);
            s0 += u.x; s1 += u.y;
        }
        float inv = (c > 0) ? (1.0f / (float)c) : 0.0f;
        float v0 = fmaxf(s0 * inv + b0, 0.0f);
        float v1 = fmaxf(s1 * inv + b1, 0.0f);
        *(__half2*)&g_prebn[(size_t)f * C_OUT + 2 * lane] = __floats2half2_rn(v0, v1);
    }
}

// ================= BN stats over prebn =================
__global__ void stats_kernel(int F) {
    __shared__ float ssum[64], ssq[64];
    int tid = threadIdx.x;
    if (tid < 64) { ssum[tid] = 0.0f; ssq[tid] = 0.0f; }
    __syncthreads();

    int cp = tid & 31;
    float s0 = 0, s1 = 0, q0 = 0, q1 = 0;
    int idx = blockIdx.x * blockDim.x + tid;
    int total = F * 32;
    int stride = gridDim.x * blockDim.x;
    for (; idx < total; idx += stride) {
        float2 v = __half22float2(((const __half2*)g_prebn)[idx]);
        s0 += v.x; s1 += v.y;
        q0 += v.x * v.x; q1 += v.y * v.y;
    }
    atomicAdd(&ssum[2 * cp], s0); atomicAdd(&ssum[2 * cp + 1], s1);
    atomicAdd(&ssq[2 * cp],  q0); atomicAdd(&ssq[2 * cp + 1],  q1);
    __syncthreads();
    if (tid < 64) {
        atomicAdd(&g_stats[tid],      ssum[tid]);
        atomicAdd(&g_stats[64 + tid], ssq[tid]);
    }
}

// ================= batchnorm apply (fp16 in, fp32 out) =================
__global__ void bn_kernel(const float* __restrict__ gamma,
                          const float* __restrict__ beta,
                          float* __restrict__ out, int F) {
    int idx = blockIdx.x * blockDim.x + threadIdx.x;
    int total = F * (C_OUT / 4);
    float invF = 1.0f / (float)F;
    for (; idx < total; idx += gridDim.x * blockDim.x) {
        int o = (idx & 15) * 4;
        uint2 raw = *(const uint2*)&g_prebn[(size_t)idx * 4];
        float2 v01 = __half22float2(*(__half2*)&raw.x);
        float2 v23 = __half22float2(*(__half2*)&raw.y);
        float vv[4] = {v01.x, v01.y, v23.x, v23.y};
        float4 r;
        #pragma unroll
        for (int j = 0; j < 4; j++) {
            float mu  = g_stats[o + j] * invF;
            float var = g_stats[C_OUT + o + j] * invF - mu * mu;
            float sc  = rsqrtf(var + BN_EPS) * gamma[o + j];
            float bb  = beta[o + j];
            (&r.x)[j] = (vv[j] - mu) * sc + bb;
        }
        *(float4*)&out[(size_t)idx * 4] = r;
    }
}

// ================= launch =================
extern "C" void kernel_launch(void* const* d_in, const int* in_sizes, int n_in,
                              void* d_out, int out_size) {
    const float* X     = (const float*)d_in[0];
    const float* BARY  = (const float*)d_in[1];
    const float* W     = (const float*)d_in[2];
    const float* bias  = (const float*)d_in[3];
    const float* gamma = (const float*)d_in[4];
    const float* beta  = (const float*)d_in[5];
    const int*   cnt   = (const int*)d_in[6];

    int T = in_sizes[0] / C_IN;
    int F = in_sizes[6];
    int numTiles = (T + TILE_M - 1) / TILE_M;

    int sms = 148;
    cudaDeviceGetAttribute(&sms, cudaDevAttrMultiProcessorCount, 0);
    cudaFuncSetAttribute(gemm_mma_kernel, cudaFuncAttributeMaxDynamicSharedMemorySize, SMEM_GEMM);

    int nb = (F + 1023) / 1024;
    scan1_kernel<<<nb, 1024>>>(cnt, F);
    scan2_kernel<<<1, 1024>>>(nb);
    scan3_kernel<<<nb, 1024>>>(cnt, F);   // offsets + flag + zero stats

    gemm_mma_kernel<<<2 * sms, 256, SMEM_GEMM>>>(X, BARY, W, bias, T, F, numTiles);

    facet_kernel<<<2048, 256>>>(cnt, bias, F);   // early-exits when flag==1

    stats_kernel<<<512, 256>>>(F);
    bn_kernel<<<2048, 256>>>(gamma, beta, (float*)d_out, F);
}

// round 13
// speedup vs baseline: 1.9303x; 1.3002x over previous
#include <cuda_runtime.h>
#include <cuda_fp16.h>
#include <math.h>
#include <stdint.h>

#define C_IN   64
#define C_OUT  64
#define NBASIS 9
#define TILE_M 128
#define MAX_T  1600000
#define MAX_F  400000
#define BN_EPS 1e-3f

// ---- scratch (device globals; no allocation allowed) ----
__device__ __half g_contrib[(size_t)MAX_T * C_OUT];  // fallback path only
__device__ __half g_prebn[(size_t)MAX_F * C_OUT];    // 51.2 MB (fp16)
__device__ int    g_offs[MAX_F];
__device__ int    g_blk[1024];
__device__ float  g_stats[2 * C_OUT];
__device__ int    g_flag;                             // 1 if all counts == 4

// ================= exclusive-scan of num_texture =================
__global__ void scan1_kernel(const int* __restrict__ cnt, int F) {
    __shared__ int s[1024];
    int tid = threadIdx.x;
    int f = blockIdx.x * 1024 + tid;
    int c = (f < F) ? cnt[f] : 0;
    s[tid] = c;
    __syncthreads();
    for (int off = 1; off < 1024; off <<= 1) {
        int v = (tid >= off) ? s[tid - off] : 0;
        __syncthreads();
        s[tid] += v;
        __syncthreads();
    }
    if (f < F) g_offs[f] = s[tid] - c;
    if (tid == 1023) g_blk[blockIdx.x] = s[1023];
}
__global__ void scan2_kernel(int nb) {
    __shared__ int s[1024];
    int tid = threadIdx.x;
    int c = (tid < nb) ? g_blk[tid] : 0;
    s[tid] = c;
    __syncthreads();
    for (int off = 1; off < 1024; off <<= 1) {
        int v = (tid >= off) ? s[tid - off] : 0;
        __syncthreads();
        s[tid] += v;
        __syncthreads();
    }
    if (tid < nb) g_blk[tid] = s[tid] - c;
    if (tid == 0) g_flag = 1;
}
__global__ void scan3_kernel(const int* __restrict__ cnt, int F) {
    int f = blockIdx.x * 1024 + threadIdx.x;
    bool ok = true;
    if (f < F) {
        g_offs[f] += g_blk[blockIdx.x];
        ok = (cnt[f] == 4);
    }
    if (blockIdx.x == 0 && threadIdx.x < 2 * C_OUT) g_stats[threadIdx.x] = 0.0f;
    if (!__syncthreads_and(ok ? 1 : 0)) {
        if (threadIdx.x == 0) g_flag = 0;
    }
}

// ================= shared helpers =================
#define MMA16816(d, a0, a1, a2, a3, b0, b1)                                 \
    asm volatile(                                                           \
        "mma.sync.aligned.m16n8k16.row.col.f32.f16.f16.f32 "                \
        "{%0,%1,%2,%3},{%4,%5,%6,%7},{%8,%9},{%0,%1,%2,%3};"                \
        : "+f"((d)[0]), "+f"((d)[1]), "+f"((d)[2]), "+f"((d)[3])            \
        : "r"(a0), "r"(a1), "r"(a2), "r"(a3), "r"(b0), "r"(b1))

__device__ __forceinline__ void ldsm4(uint32_t* r, uint32_t addr) {
    asm volatile("ldmatrix.sync.aligned.m8n8.x4.shared.b16 {%0,%1,%2,%3}, [%4];"
                 : "=r"(r[0]), "=r"(r[1]), "=r"(r[2]), "=r"(r[3]) : "r"(addr));
}
__device__ __forceinline__ uint32_t hmul2u(uint32_t a, uint32_t b) {
    __half2 r = __hmul2(*(__half2*)&a, *(__half2*)&b);
    return *(uint32_t*)&r;
}
__device__ __forceinline__ uint32_t hfma2u(uint32_t a, uint32_t b, uint32_t c) {
    __half2 r = __hfma2(*(__half2*)&a, *(__half2*)&b, *(__half2*)&c);
    return *(uint32_t*)&r;
}

// ================= FUSED kernel (counts all == 4) ==========================
// Z[f, i, k] = sum_{j=0..3} x[4f+j, i] * bary[4f+j, k]   (fp16, in SMEM)
// facetsum[f, o] = sum_{i,k} Z[f,i,k] * W[o,i,k]          (tensor cores)
// prebn[f, o]   = relu(facetsum * 0.25 + bias)
//
// Tile = 128 facets (512 textures). SMEM:
//   Z : 128 rows x 1168 B (576 halfs + 16B pad; odd 16B-mult -> no swizzle)
//   W : R12 layout, [kb*64+o] rows of 128B, XOR-swizzled     = 73728 B
#define TILE_TX   512
#define TILE_F    128
#define ZSTR      1168
#define SM_Z      0
#define SM_W2     149504                 // 128 * 1168
#define SMEM_FUSED 223232                // + 73728

__global__ void __launch_bounds__(512, 1) gemm_fused_kernel(
    const float* __restrict__ X,     // [T, 64]
    const float* __restrict__ BARY,  // [T, 9]
    const float* __restrict__ W,     // [64, 64, 9]
    const float* __restrict__ BIAS,  // [64]
    int T, int F, int numTiles)
{
    if (g_flag == 0) return;
    extern __shared__ char sm[];
    const uint32_t smb = (uint32_t)__cvta_generic_to_shared(sm);

    const int tid  = threadIdx.x;
    const int wid  = tid >> 5;
    const int lane = tid & 31;
    const int gid  = lane >> 2;
    const int tid4 = lane & 3;
    const int warp_m = wid >> 2;     // 0..3 : 32-facet band
    const int warp_n = wid & 3;      // 0..3 : 16-col band

    // ---- W fp16 convert (R12 swizzled layout) ----
    for (int idx = tid; idx < C_OUT * C_IN * NBASIS; idx += 512) {
        int o   = idx / (C_IN * NBASIS);
        int rem = idx - o * (C_IN * NBASIS);
        int i   = rem / NBASIS;
        int k   = rem - i * NBASIS;
        uint32_t byte = (uint32_t)(k * 64 + o) * 128
                      + ((((uint32_t)i >> 3) ^ (uint32_t)(o & 7)) << 4)
                      + (i & 7) * 2;
        *(__half*)(sm + SM_W2 + byte) = __float2half_rn(W[idx]);
    }

    // ---- bias in registers ----
    float bia[2][2];
    #pragma unroll
    for (int nt = 0; nt < 2; nt++) {
        int col = warp_n * 16 + nt * 8 + tid4 * 2;
        bia[nt][0] = BIAS[col];
        bia[nt][1] = BIAS[col + 1];
    }

    // ---- LDSM addresses ----
    uint32_t aBase[2];
    #pragma unroll
    for (int mt = 0; mt < 2; mt++)
        aBase[mt] = smb + SM_Z
                  + (uint32_t)(warp_m * 32 + mt * 16 + (lane & 15)) * ZSTR
                  + ((uint32_t)(lane >> 4) << 4);
    const int n_local = warp_n * 16 + ((lane >> 4) & 1) * 8 + (lane & 7);
    const uint32_t bRow = smb + SM_W2 + (uint32_t)n_local * 128;
    const int kh  = (lane >> 3) & 1;
    const int nsw = n_local & 7;

    // ---- construction ids: thread = (facet fq, channel-quarter q) ----
    const int fq = tid >> 2;         // 0..127
    const int q  = tid & 3;

    uint32_t xh[4][4][2];            // [texture j][cc][half2] : ch = cc*16+q*4+..
    float    br[9];                  // bary of texture (fq*4 + q)

    int tile = blockIdx.x;
    // ---- prologue prefetch (tile 0) ----
    {
        #pragma unroll
        for (int j = 0; j < 4; j++) {
            int t = tile * TILE_TX + fq * 4 + j;
            if (t < T) {
                const float4* xp = (const float4*)(X + (size_t)t * C_IN + q * 4);
                #pragma unroll
                for (int cc = 0; cc < 4; cc++) {
                    float4 v = xp[cc * 4];
                    __half2 h0 = __floats2half2_rn(v.x, v.y);
                    __half2 h1 = __floats2half2_rn(v.z, v.w);
                    xh[j][cc][0] = *(uint32_t*)&h0;
                    xh[j][cc][1] = *(uint32_t*)&h1;
                }
            } else {
                #pragma unroll
                for (int cc = 0; cc < 4; cc++) { xh[j][cc][0] = 0u; xh[j][cc][1] = 0u; }
            }
        }
        int tb = tile * TILE_TX + fq * 4 + q;
        #pragma unroll
        for (int k = 0; k < NBASIS; k++)
            br[k] = (tb < T) ? BARY[(size_t)tb * NBASIS + k] : 0.0f;
    }
    __syncthreads();   // W visible

    for (; tile < numTiles; tile += gridDim.x) {

        // ---- construct Z (fp16, quad-shuffle bary broadcast) ----
        const uint32_t zbase = smb + SM_Z + (uint32_t)fq * ZSTR + q * 8;
        #pragma unroll
        for (int k = 0; k < NBASIS; k++) {
            uint32_t ac[4][2];
            #pragma unroll
            for (int j = 0; j < 4; j++) {
                float bf = __shfl_sync(0xFFFFFFFFu, br[k], (lane & ~3) | j);
                __half2 hb = __half2half2(__float2half_rn(bf));
                uint32_t bb = *(uint32_t*)&hb;
                #pragma unroll
                for (int cc = 0; cc < 4; cc++) {
                    if (j == 0) {
                        ac[cc][0] = hmul2u(xh[0][cc][0], bb);
                        ac[cc][1] = hmul2u(xh[0][cc][1], bb);
                    } else {
                        ac[cc][0] = hfma2u(xh[j][cc][0], bb, ac[cc][0]);
                        ac[cc][1] = hfma2u(xh[j][cc][1], bb, ac[cc][1]);
                    }
                }
            }
            #pragma unroll
            for (int cc = 0; cc < 4; cc++)
                asm volatile("st.shared.v2.b32 [%0], {%1, %2};"
                             :: "r"(zbase + k * 128 + cc * 32),
                                "r"(ac[cc][0]), "r"(ac[cc][1]) : "memory");
        }
        __syncthreads();   // barrier A: Z visible

        // ---- prefetch next tile (hidden under GEMM) ----
        {
            int ntile = tile + gridDim.x;
            if (ntile < numTiles) {
                #pragma unroll
                for (int j = 0; j < 4; j++) {
                    int t = ntile * TILE_TX + fq * 4 + j;
                    if (t < T) {
                        const float4* xp = (const float4*)(X + (size_t)t * C_IN + q * 4);
                        #pragma unroll
                        for (int cc = 0; cc < 4; cc++) {
                            float4 v = xp[cc * 4];
                            __half2 h0 = __floats2half2_rn(v.x, v.y);
                            __half2 h1 = __floats2half2_rn(v.z, v.w);
                            xh[j][cc][0] = *(uint32_t*)&h0;
                            xh[j][cc][1] = *(uint32_t*)&h1;
                        }
                    } else {
                        #pragma unroll
                        for (int cc = 0; cc < 4; cc++) { xh[j][cc][0] = 0u; xh[j][cc][1] = 0u; }
                    }
                }
                int tb = ntile * TILE_TX + fq * 4 + q;
                #pragma unroll
                for (int k = 0; k < NBASIS; k++)
                    br[k] = (tb < T) ? BARY[(size_t)tb * NBASIS + k] : 0.0f;
            }
        }

        // ---- GEMM: facetsum[128,64] = Z @ W^T ----
        float acc[2][2][4];
        #pragma unroll
        for (int mt = 0; mt < 2; mt++)
            #pragma unroll
            for (int nt = 0; nt < 2; nt++)
                #pragma unroll
                for (int e = 0; e < 4; e++) acc[mt][nt][e] = 0.0f;

        #pragma unroll 4
        for (int kc = 0; kc < 36; kc++) {
            int kb = kc >> 2, ks = kc & 3;
            uint32_t a0[4], a1[4], b[4];
            ldsm4(a0, aBase[0] + kc * 32);
            ldsm4(a1, aBase[1] + kc * 32);
            ldsm4(b, bRow + kb * 8192 + ((uint32_t)((ks * 2 + kh) ^ nsw) << 4));
            MMA16816(acc[0][0], a0[0], a0[1], a0[2], a0[3], b[0], b[1]);
            MMA16816(acc[0][1], a0[0], a0[1], a0[2], a0[3], b[2], b[3]);
            MMA16816(acc[1][0], a1[0], a1[1], a1[2], a1[3], b[0], b[1]);
            MMA16816(acc[1][1], a1[0], a1[1], a1[2], a1[3], b[2], b[3]);
        }

        // ---- epilogue: mean + bias + relu -> prebn ----
        int f0 = tile * TILE_F + warp_m * 32;
        #pragma unroll
        for (int mt = 0; mt < 2; mt++) {
            int fA = f0 + mt * 16 + gid;
            #pragma unroll
            for (int nt = 0; nt < 2; nt++) {
                int col = warp_n * 16 + nt * 8 + tid4 * 2;
                if (fA < F) {
                    float v0 = fmaxf(acc[mt][nt][0] * 0.25f + bia[nt][0], 0.0f);
                    float v1 = fmaxf(acc[mt][nt][1] * 0.25f + bia[nt][1], 0.0f);
                    *(__half2*)&g_prebn[(size_t)fA * C_OUT + col] = __floats2half2_rn(v0, v1);
                }
                if (fA + 8 < F) {
                    float v0 = fmaxf(acc[mt][nt][2] * 0.25f + bia[nt][0], 0.0f);
                    float v1 = fmaxf(acc[mt][nt][3] * 0.25f + bia[nt][1], 0.0f);
                    *(__half2*)&g_prebn[(size_t)(fA + 8) * C_OUT + col] = __floats2half2_rn(v0, v1);
                }
            }
        }
        __syncthreads();   // barrier B: all Z reads done before next construct
    }
}

// ================= FALLBACK GEMM (general counts; R8/R12 core) =============
#define SM_W      0
#define SM_AX     73728
#define SM_BS     92160
#define BS_HALFS  1188
#define SMEM_GEMM 96912

__global__ void __launch_bounds__(256, 2) gemm_fallback_kernel(
    const float* __restrict__ X, const float* __restrict__ BARY,
    const float* __restrict__ W, int T, int numTiles)
{
    if (g_flag != 0) return;
    extern __shared__ char sm[];
    const uint32_t smb = (uint32_t)__cvta_generic_to_shared(sm);
    __half* Bsh = (__half*)(sm + SM_BS);

    const int tid  = threadIdx.x;
    const int wid  = tid >> 5;
    const int lane = tid & 31;
    const int gid  = lane >> 2;
    const int warp_m = wid >> 1;
    const int warp_n = wid & 1;
    const int rbase  = warp_m * 32;

    for (int idx = tid; idx < C_OUT * C_IN * NBASIS; idx += 256) {
        int o   = idx / (C_IN * NBASIS);
        int rem = idx - o * (C_IN * NBASIS);
        int i   = rem / NBASIS;
        int k   = rem - i * NBASIS;
        uint32_t byte = (uint32_t)(k * 64 + o) * 128
                      + ((((uint32_t)i >> 3) ^ (uint32_t)(o & 7)) << 4)
                      + (i & 7) * 2;
        *(__half*)(sm + SM_W + byte) = __float2half_rn(W[idx]);
    }

    uint32_t a_base[2];
    #pragma unroll
    for (int mt = 0; mt < 2; mt++)
        a_base[mt] = smb + SM_AX
                   + (uint32_t)(rbase + mt * 16 + (lane & 15)) * 144
                   + ((lane >> 4) << 4);
    uint32_t b_base[2];
    int s_p[2];
    const int kh = (lane >> 3) & 1;
    #pragma unroll
    for (int p = 0; p < 2; p++) {
        int n_local = warp_n * 32 + p * 16 + ((lane >> 4) & 1) * 8 + (lane & 7);
        b_base[p] = smb + SM_W + (uint32_t)n_local * 128;
        s_p[p] = n_local & 7;
    }

    const int prow = tid >> 1;
    const int phf  = tid & 1;
    const int kb0  = phf ? 5 : 0;
    const int nby  = phf ? 4 : 5;

    uint32_t pk[16];
    float    by[5];

    int tile = blockIdx.x;
    {
        int t = tile * TILE_M + prow;
        if (t < T) {
            const float4* xp = (const float4*)(X + (size_t)t * C_IN + phf * 32);
            #pragma unroll
            for (int j = 0; j < 8; j++) {
                float4 v = xp[j];
                __half2 h0 = __floats2half2_rn(v.x, v.y);
                __half2 h1 = __floats2half2_rn(v.z, v.w);
                pk[2 * j]     = *(uint32_t*)&h0;
                pk[2 * j + 1] = *(uint32_t*)&h1;
            }
            #pragma unroll
            for (int j = 0; j < 5; j++)
                if (j < nby) by[j] = BARY[(size_t)t * NBASIS + kb0 + j];
        } else {
            #pragma unroll
            for (int j = 0; j < 16; j++) pk[j] = 0u;
            #pragma unroll
            for (int j = 0; j < 5; j++) by[j] = 0.0f;
        }
    }
    __syncthreads();

    int buf = 0;
    for (; tile < numTiles; tile += gridDim.x) {
        const int t0 = tile * TILE_M;
        {
            uint4* dst = (uint4*)(sm + SM_AX + prow * 144 + phf * 64);
            #pragma unroll
            for (int c = 0; c < 4; c++)
                dst[c] = make_uint4(pk[4 * c], pk[4 * c + 1], pk[4 * c + 2], pk[4 * c + 3]);
            __half* BsB = Bsh + buf * BS_HALFS;
            #pragma unroll
            for (int j = 0; j < 5; j++)
                if (j < nby) BsB[(kb0 + j) * 132 + prow] = __float2half_rn(by[j]);
        }
        __syncthreads();

        uint32_t afr[2][4][4];
        #pragma unroll
        for (int mt = 0; mt < 2; mt++)
            #pragma unroll
            for (int ks = 0; ks < 4; ks++)
                ldsm4(afr[mt][ks], a_base[mt] + ks * 32);
        __syncthreads();

        {
            int ntile = tile + gridDim.x;
            if (ntile < numTiles) {
                int t = ntile * TILE_M + prow;
                if (t < T) {
                    const float4* xp = (const float4*)(X + (size_t)t * C_IN + phf * 32);
                    #pragma unroll
                    for (int j = 0; j < 8; j++) {
                        float4 v = xp[j];
                        __half2 h0 = __floats2half2_rn(v.x, v.y);
                        __half2 h1 = __floats2half2_rn(v.z, v.w);
                        pk[2 * j]     = *(uint32_t*)&h0;
                        pk[2 * j + 1] = *(uint32_t*)&h1;
                    }
                    #pragma unroll
                    for (int j = 0; j < 5; j++)
                        if (j < nby) by[j] = BARY[(size_t)t * NBASIS + kb0 + j];
                } else {
                    #pragma unroll
                    for (int j = 0; j < 16; j++) pk[j] = 0u;
                    #pragma unroll
                    for (int j = 0; j < 5; j++) by[j] = 0.0f;
                }
            }
        }

        const __half* BsB = Bsh + buf * BS_HALFS;
        float acc[2][4][4];
        #pragma unroll
        for (int mt = 0; mt < 2; mt++)
            #pragma unroll
            for (int nt = 0; nt < 4; nt++)
                #pragma unroll
                for (int e = 0; e < 4; e++) acc[mt][nt][e] = 0.0f;

        #pragma unroll 1
        for (int kb = 0; kb < NBASIS; kb++) {
            uint32_t bb0[2], bb1[2];
            #pragma unroll
            for (int mt = 0; mt < 2; mt++) {
                int r = rbase + mt * 16 + gid;
                __half2 h0 = __half2half2(BsB[kb * 132 + r]);
                __half2 h1 = __half2half2(BsB[kb * 132 + r + 8]);
                bb0[mt] = *(uint32_t*)&h0;
                bb1[mt] = *(uint32_t*)&h1;
            }
            const uint32_t kb_off = (uint32_t)kb * 8192;
            #pragma unroll
            for (int ks = 0; ks < 4; ks++) {
                uint32_t sa0[4], sa1[4];
                sa0[0] = hmul2u(afr[0][ks][0], bb0[0]);
                sa0[1] = hmul2u(afr[0][ks][1], bb1[0]);
                sa0[2] = hmul2u(afr[0][ks][2], bb0[0]);
                sa0[3] = hmul2u(afr[0][ks][3], bb1[0]);
                sa1[0] = hmul2u(afr[1][ks][0], bb0[1]);
                sa1[1] = hmul2u(afr[1][ks][1], bb1[1]);
                sa1[2] = hmul2u(afr[1][ks][2], bb0[1]);
                sa1[3] = hmul2u(afr[1][ks][3], bb1[1]);
                #pragma unroll
                for (int p = 0; p < 2; p++) {
                    uint32_t b[4];
                    uint32_t chunk = (uint32_t)(((ks << 1) | kh) ^ s_p[p]) << 4;
                    ldsm4(b, b_base[p] + kb_off + chunk);
                    MMA16816(acc[0][2 * p],     sa0[0], sa0[1], sa0[2], sa0[3], b[0], b[1]);
                    MMA16816(acc[1][2 * p],     sa1[0], sa1[1], sa1[2], sa1[3], b[0], b[1]);
                    MMA16816(acc[0][2 * p + 1], sa0[0], sa0[1], sa0[2], sa0[3], b[2], b[3]);
                    MMA16816(acc[1][2 * p + 1], sa1[0], sa1[1], sa1[2], sa1[3], b[2], b[3]);
                }
            }
        }

        const int tid4 = lane & 3;
        #pragma unroll
        for (int mt = 0; mt < 2; mt++) {
            int t = t0 + rbase + mt * 16 + gid;
            #pragma unroll
            for (int nt = 0; nt < 4; nt++) {
                int col = warp_n * 32 + nt * 8 + tid4 * 2;
                if (t < T)
                    *(__half2*)&g_contrib[(size_t)t * C_OUT + col] =
                        __floats2half2_rn(acc[mt][nt][0], acc[mt][nt][1]);
                if (t + 8 < T)
                    *(__half2*)&g_contrib[(size_t)(t + 8) * C_OUT + col] =
                        __floats2half2_rn(acc[mt][nt][2], acc[mt][nt][3]);
            }
        }
        buf ^= 1;
    }
}

// ================= facet fallback (general counts) ==========================
__global__ void facet_kernel(const int* __restrict__ cnt,
                             const float* __restrict__ bias, int F) {
    if (g_flag) return;
    int tid  = threadIdx.x;
    int gw   = (blockIdx.x * blockDim.x + tid) >> 5;
    int lane = tid & 31;
    int nw   = (gridDim.x * blockDim.x) >> 5;
    float b0 = bias[2 * lane];
    float b1 = bias[2 * lane + 1];
    for (int f = gw; f < F; f += nw) {
        int start = g_offs[f];
        int c = cnt[f];
        float s0 = 0.0f, s1 = 0.0f;
        for (int r = 0; r < c; r++) {
            float2 u = __half22float2(((const __half2*)(g_contrib + (size_t)(start + r) * C_OUT))[lane]);
            s0 += u.x; s1 += u.y;
        }
        float inv = (c > 0) ? (1.0f / (float)c) : 0.0f;
        float v0 = fmaxf(s0 * inv + b0, 0.0f);
        float v1 = fmaxf(s1 * inv + b1, 0.0f);
        *(__half2*)&g_prebn[(size_t)f * C_OUT + 2 * lane] = __floats2half2_rn(v0, v1);
    }
}

// ================= BN stats over prebn =================
__global__ void stats_kernel(int F) {
    __shared__ float ssum[64], ssq[64];
    int tid = threadIdx.x;
    if (tid < 64) { ssum[tid] = 0.0f; ssq[tid] = 0.0f; }
    __syncthreads();

    int cp = tid & 31;
    float s0 = 0, s1 = 0, q0 = 0, q1 = 0;
    int idx = blockIdx.x * blockDim.x + tid;
    int total = F * 32;
    int stride = gridDim.x * blockDim.x;
    for (; idx < total; idx += stride) {
        float2 v = __half22float2(((const __half2*)g_prebn)[idx]);
        s0 += v.x; s1 += v.y;
        q0 += v.x * v.x; q1 += v.y * v.y;
    }
    atomicAdd(&ssum[2 * cp], s0); atomicAdd(&ssum[2 * cp + 1], s1);
    atomicAdd(&ssq[2 * cp],  q0); atomicAdd(&ssq[2 * cp + 1],  q1);
    __syncthreads();
    if (tid < 64) {
        atomicAdd(&g_stats[tid],      ssum[tid]);
        atomicAdd(&g_stats[64 + tid], ssq[tid]);
    }
}

// ================= batchnorm apply (fp16 in, fp32 out) =================
__global__ void bn_kernel(const float* __restrict__ gamma,
                          const float* __restrict__ beta,
                          float* __restrict__ out, int F) {
    int idx = blockIdx.x * blockDim.x + threadIdx.x;
    int total = F * (C_OUT / 4);
    float invF = 1.0f / (float)F;
    for (; idx < total; idx += gridDim.x * blockDim.x) {
        int o = (idx & 15) * 4;
        uint2 raw = *(const uint2*)&g_prebn[(size_t)idx * 4];
        float2 v01 = __half22float2(*(__half2*)&raw.x);
        float2 v23 = __half22float2(*(__half2*)&raw.y);
        float vv[4] = {v01.x, v01.y, v23.x, v23.y};
        float4 r;
        #pragma unroll
        for (int j = 0; j < 4; j++) {
            float mu  = g_stats[o + j] * invF;
            float var = g_stats[C_OUT + o + j] * invF - mu * mu;
            float sc  = rsqrtf(var + BN_EPS) * gamma[o + j];
            float bb  = beta[o + j];
            (&r.x)[j] = (vv[j] - mu) * sc + bb;
        }
        *(float4*)&out[(size_t)idx * 4] = r;
    }
}

// ================= launch =================
extern "C" void kernel_launch(void* const* d_in, const int* in_sizes, int n_in,
                              void* d_out, int out_size) {
    const float* X     = (const float*)d_in[0];
    const float* BARY  = (const float*)d_in[1];
    const float* W     = (const float*)d_in[2];
    const float* bias  = (const float*)d_in[3];
    const float* gamma = (const float*)d_in[4];
    const float* beta  = (const float*)d_in[5];
    const int*   cnt   = (const int*)d_in[6];

    int T = in_sizes[0] / C_IN;
    int F = in_sizes[6];
    int numTilesFB = (T + TILE_M - 1) / TILE_M;
    int numTilesFU = (T + TILE_TX - 1) / TILE_TX;

    int sms = 148;
    cudaDeviceGetAttribute(&sms, cudaDevAttrMultiProcessorCount, 0);
    cudaFuncSetAttribute(gemm_fused_kernel, cudaFuncAttributeMaxDynamicSharedMemorySize, SMEM_FUSED);
    cudaFuncSetAttribute(gemm_fallback_kernel, cudaFuncAttributeMaxDynamicSharedMemorySize, SMEM_GEMM);

    int nb = (F + 1023) / 1024;
    scan1_kernel<<<nb, 1024>>>(cnt, F);
    scan2_kernel<<<1, 1024>>>(nb);
    scan3_kernel<<<nb, 1024>>>(cnt, F);   // offsets + flag + zero stats

    gemm_fused_kernel<<<sms, 512, SMEM_FUSED>>>(X, BARY, W, bias, T, F, numTilesFU);
    gemm_fallback_kernel<<<2 * sms, 256, SMEM_GEMM>>>(X, BARY, W, T, numTilesFB);
    facet_kernel<<<2048, 256>>>(cnt, bias, F);

    stats_kernel<<<512, 256>>>(F);
    bn_kernel<<<2048, 256>>>(gamma, beta, (float*)d_out, F);
}